// round 14
// baseline (speedup 1.0000x reference)
#include <cuda_runtime.h>
#include <cstdint>

#define MAXN 100000
#define MAXE 1600000
#define MAXG 2048
#define H 64
#define NB_MAX ((MAXN + 255) / 256 + 1)

typedef unsigned long long u64;

// f32x2 packed math (Blackwell sm_103a): FFMA2 doubles fp32 FLOPs per instr.
#define FMA2(d, a, b, c) \
    asm("fma.rn.f32x2 %0, %1, %2, %3;" : "=l"(d) : "l"(a), "l"(b), "l"(c))
#define DUP2(d, s) \
    asm("mov.b64 %0, {%1, %1};" : "=l"(d) : "r"(s))
#define UNPK2(lo, hi, s) \
    asm("mov.b64 {%0, %1}, %2;" : "=r"(lo), "=r"(hi) : "l"(s))

// ---------------- scratch (device globals; start zero-initialized) ---------
__device__ float  g_h[MAXN * H];        // node features (ping)
__device__ float  g_h2[MAXN * H];       // node features (pong)
__device__ int    g_cnt[MAXN];          // in-degree histogram (self-cleaned)
__device__ int    g_off[MAXN + 1];      // CSR offsets by dst
__device__ int    g_cur[MAXN];          // running cursors for fill
__device__ int    g_bsum[NB_MAX];       // scan block sums
__device__ int    g_src[MAXE];          // CSR-ordered source node ids
__device__ float4 g_ea[MAXE];           // CSR-ordered edge attributes
__device__ float  g_sums[MAXG * H];     // graph pooling sums (self-cleaned)
__device__ float  g_cntf[MAXG];         // graph node counts
__device__ int    g_tilectr[8];         // layer tile-steal counters (self-cleaned)

// ---------------- CSR build -------------------------------------------------
__global__ void hist_kernel(const int* __restrict__ dst, int nedges) {
    for (int i = blockIdx.x * blockDim.x + threadIdx.x; i < nedges; i += gridDim.x * blockDim.x)
        atomicAdd(&g_cnt[dst[i]], 1);
}

// phase 1: block-local exclusive scan of g_cnt chunks; block totals -> g_bsum
__global__ void scan1_kernel(int n) {
    __shared__ int wsum[8];
    int tid = threadIdx.x, lane = tid & 31, w = tid >> 5;
    int i = blockIdx.x * 256 + tid;
    int v = (i < n) ? g_cnt[i] : 0;
    int x = v;
    #pragma unroll
    for (int d = 1; d < 32; d <<= 1) {
        int y = __shfl_up_sync(0xffffffffu, x, d);
        if (lane >= d) x += y;
    }
    if (lane == 31) wsum[w] = x;
    __syncthreads();
    if (w == 0 && lane < 8) {
        int sv = wsum[lane];
        #pragma unroll
        for (int d = 1; d < 8; d <<= 1) {
            int y = __shfl_up_sync(0xffu, sv, d);
            if (lane >= d) sv += y;
        }
        wsum[lane] = sv;
    }
    __syncthreads();
    int pre = (w == 0) ? 0 : wsum[w - 1];
    if (i < n) g_off[i] = pre + x - v;       // local exclusive
    if (tid == 255) g_bsum[blockIdx.x] = wsum[7];
}

// phase 2: single block exclusive-scans the nb block sums in place, total -> g_off[n]
__global__ void scan2_kernel(int nb, int n) {
    __shared__ int wsum[8];
    __shared__ int s_carry;
    int tid = threadIdx.x, lane = tid & 31, w = tid >> 5;
    if (tid == 0) s_carry = 0;
    __syncthreads();
    int nchunk = (nb + 255) >> 8;
    for (int c = 0; c < nchunk; c++) {
        int i = (c << 8) + tid;
        int v = (i < nb) ? g_bsum[i] : 0;
        int x = v;
        #pragma unroll
        for (int d = 1; d < 32; d <<= 1) {
            int y = __shfl_up_sync(0xffffffffu, x, d);
            if (lane >= d) x += y;
        }
        if (lane == 31) wsum[w] = x;
        __syncthreads();
        if (w == 0 && lane < 8) {
            int sv = wsum[lane];
            #pragma unroll
            for (int d = 1; d < 8; d <<= 1) {
                int y = __shfl_up_sync(0xffu, sv, d);
                if (lane >= d) sv += y;
            }
            wsum[lane] = sv;
        }
        __syncthreads();
        int pre = (w == 0) ? 0 : wsum[w - 1];
        int carry = s_carry;
        if (i < nb) g_bsum[i] = carry + pre + x - v;
        __syncthreads();
        if (tid == 0) s_carry = carry + wsum[7];
        __syncthreads();
    }
    if (tid == 0) g_off[n] = s_carry;
}

// phase 3: add block offsets; mirror to g_cur
__global__ void scan3_kernel(int n) {
    int i = blockIdx.x * blockDim.x + threadIdx.x;
    if (i < n) {
        int o = g_off[i] + g_bsum[i >> 8];
        g_off[i] = o;
        g_cur[i] = o;
    }
}

// Merged kernel: blocks [0, FILL_BLKS) fill CSR (and re-zero g_cnt for the
// next call); blocks [FILL_BLKS, FILL_BLKS+PROJ_BLKS) do the input projection.
#define FILL_BLKS 2048
#define PROJ_BLKS 1184
__global__ void fillproj_kernel(const int* __restrict__ src, const int* __restrict__ dst,
                                const float* __restrict__ edge_attr, int nedges,
                                const float* __restrict__ x,
                                const float* __restrict__ W, const float* __restrict__ b,
                                int n) {
    if (blockIdx.x < FILL_BLKS) {
        int i0 = blockIdx.x * blockDim.x + threadIdx.x;
        int stride = FILL_BLKS * blockDim.x;
        for (int i = i0; i < nedges; i += stride) {
            int d = dst[i];
            int p = atomicAdd(&g_cur[d], 1);
            g_src[p] = src[i];
            g_ea[p] = __ldg((const float4*)(edge_attr + (size_t)i * 4));
        }
        for (int i = i0; i < n; i += stride) g_cnt[i] = 0;   // clean for next call
        return;
    }
    // ---- input projection: h = relu(x @ W_in + b_in), x:[n,32] W:[32,64]
    __shared__ float sW[32 * 64];
    __shared__ float sb[64];
    __shared__ float sx[4][32];
    int tid = threadIdx.x;
    for (int i = tid; i < 32 * 64; i += 256) sW[i] = W[i];
    if (tid < 64) sb[tid] = b[tid];
    __syncthreads();
    int s = tid >> 6, j = tid & 63;
    int ntiles = (n + 3) >> 2;
    for (int tile = blockIdx.x - FILL_BLKS; tile < ntiles; tile += PROJ_BLKS) {
        int base = tile * 4;
        if (tid < 128) {
            int node = base + (tid >> 5);
            sx[tid >> 5][tid & 31] = (node < n) ? x[(size_t)node * 32 + (tid & 31)] : 0.f;
        }
        __syncthreads();
        float acc = sb[j];
        #pragma unroll
        for (int k = 0; k < 32; k++) acc = fmaf(sx[s][k], sW[k * 64 + j], acc);
        int node = base + s;
        if (node < n) g_h[(size_t)node * H + j] = fmaxf(acc, 0.f);
        __syncthreads();
    }
}

// ---------------- fused GINE layer: agg (into smem) + MLP + optional pool ---
// R13 kernel with ONE change: the agg phase software-pipelines the src-index
// loads one 4-batch ahead. The prefetch registers are free here because the
// MLP phase already forces the 64-reg allocation (4 blocks/SM).
#define TILE_NODES 48
__global__ void __launch_bounds__(256) layer_kernel(
        const float* __restrict__ hin, float* __restrict__ hout,
        const float* __restrict__ We, const float* __restrict__ be,
        const float* __restrict__ W1, const float* __restrict__ b1,
        const float* __restrict__ W2, const float* __restrict__ b2,
        const int* __restrict__ batch, int do_pool,
        int n, int ntiles, int slot) {
    __shared__ float sW1[64 * 64];
    __shared__ float sW2[64 * 64];
    __shared__ float sz[TILE_NODES][64];
    __shared__ float sWe[4 * 64];
    __shared__ float sbe[64];
    __shared__ int s_tile;
    int tid = threadIdx.x;
    for (int i = tid; i < 64 * 64; i += 256) { sW1[i] = W1[i]; sW2[i] = W2[i]; }
    if (tid < 256) sWe[tid] = We[tid];
    if (tid < 64) sbe[tid] = be[tid];
    int jgrp = tid & 15;   // MLP output group: j = jgrp*4 (2 f32x2 pairs)
    int i0 = tid >> 4;     // MLP node slot 0..15 (others: i0+16, i0+32)
    int lane = tid & 31;   // agg ids
    int wid = tid >> 5;
    int c0 = lane * 2;
    const u64* b1p = (const u64*)b1;
    const u64* b2p = (const u64*)b2;
    u64 b1lo = __ldg(&b1p[jgrp * 2]), b1hi = __ldg(&b1p[jgrp * 2 + 1]);
    u64 b2lo = __ldg(&b2p[jgrp * 2]), b2hi = __ldg(&b2p[jgrp * 2 + 1]);
    __syncthreads();
    // agg weights into registers (per-lane channel pair)
    float w00 = sWe[0 * 64 + c0], w10 = sWe[1 * 64 + c0], w20 = sWe[2 * 64 + c0], w30 = sWe[3 * 64 + c0];
    float w01 = sWe[0 * 64 + c0 + 1], w11 = sWe[1 * 64 + c0 + 1], w21 = sWe[2 * 64 + c0 + 1], w31 = sWe[3 * 64 + c0 + 1];
    float bb0 = sbe[c0], bb1 = sbe[c0 + 1];
    const ulonglong2* W14 = (const ulonglong2*)sW1;
    const ulonglong2* W24 = (const ulonglong2*)sW2;

    for (;;) {
        if (tid == 0) s_tile = atomicAdd(&g_tilectr[slot], 1);
        __syncthreads();
        int tile = s_tile;
        if (tile >= ntiles) break;
        int base = tile * TILE_NODES;

        // ---- agg phase: warp `wid` aggregates slots [wid*6, wid*6+6)
        #pragma unroll
        for (int q = 0; q < 6; q++) {
            int slotn = wid * 6 + q;
            int node = base + slotn;
            float2 outv = make_float2(0.f, 0.f);
            if (node < n) {
                int s = g_off[node], e = g_off[node + 1];
                float a0 = 0.f, a1 = 0.f, d0 = 0.f, d1 = 0.f;
                float u0 = 0.f, u1 = 0.f, v0 = 0.f, v1 = 0.f;
                int p = s;
                int cs0, cs1, cs2, cs3;
                if (p + 4 <= e) {
                    cs0 = __ldg(&g_src[p]);
                    cs1 = __ldg(&g_src[p + 1]);
                    cs2 = __ldg(&g_src[p + 2]);
                    cs3 = __ldg(&g_src[p + 3]);
                }
                while (p + 4 <= e) {
                    // h gathers issue immediately (src indices already resident)
                    float2 h0 = __ldg((const float2*)(hin + (size_t)cs0 * H + c0));
                    float2 h1 = __ldg((const float2*)(hin + (size_t)cs1 * H + c0));
                    float2 h2 = __ldg((const float2*)(hin + (size_t)cs2 * H + c0));
                    float2 h3 = __ldg((const float2*)(hin + (size_t)cs3 * H + c0));
                    float4 q0 = __ldg(&g_ea[p]);
                    float4 q1 = __ldg(&g_ea[p + 1]);
                    float4 q2 = __ldg(&g_ea[p + 2]);
                    float4 q3 = __ldg(&g_ea[p + 3]);
                    int pn = p + 4;
                    if (pn + 4 <= e) {   // prefetch next full batch's src
                        cs0 = __ldg(&g_src[pn]);
                        cs1 = __ldg(&g_src[pn + 1]);
                        cs2 = __ldg(&g_src[pn + 2]);
                        cs3 = __ldg(&g_src[pn + 3]);
                    }
                    float e00 = fmaf(q0.x, w00, fmaf(q0.y, w10, fmaf(q0.z, w20, fmaf(q0.w, w30, bb0))));
                    float e01 = fmaf(q0.x, w01, fmaf(q0.y, w11, fmaf(q0.z, w21, fmaf(q0.w, w31, bb1))));
                    float e10 = fmaf(q1.x, w00, fmaf(q1.y, w10, fmaf(q1.z, w20, fmaf(q1.w, w30, bb0))));
                    float e11 = fmaf(q1.x, w01, fmaf(q1.y, w11, fmaf(q1.z, w21, fmaf(q1.w, w31, bb1))));
                    float e20 = fmaf(q2.x, w00, fmaf(q2.y, w10, fmaf(q2.z, w20, fmaf(q2.w, w30, bb0))));
                    float e21 = fmaf(q2.x, w01, fmaf(q2.y, w11, fmaf(q2.z, w21, fmaf(q2.w, w31, bb1))));
                    float e30 = fmaf(q3.x, w00, fmaf(q3.y, w10, fmaf(q3.z, w20, fmaf(q3.w, w30, bb0))));
                    float e31 = fmaf(q3.x, w01, fmaf(q3.y, w11, fmaf(q3.z, w21, fmaf(q3.w, w31, bb1))));
                    a0 += fmaxf(h0.x + e00, 0.f);  a1 += fmaxf(h0.y + e01, 0.f);
                    u0 += fmaxf(h1.x + e10, 0.f);  u1 += fmaxf(h1.y + e11, 0.f);
                    v0 += fmaxf(h2.x + e20, 0.f);  v1 += fmaxf(h2.y + e21, 0.f);
                    d0 += fmaxf(h3.x + e30, 0.f);  d1 += fmaxf(h3.y + e31, 0.f);
                    p = pn;
                }
                for (; p < e; ++p) {
                    int s0 = __ldg(&g_src[p]);
                    float4 q0 = __ldg(&g_ea[p]);
                    float2 h0 = __ldg((const float2*)(hin + (size_t)s0 * H + c0));
                    float e00 = fmaf(q0.x, w00, fmaf(q0.y, w10, fmaf(q0.z, w20, fmaf(q0.w, w30, bb0))));
                    float e01 = fmaf(q0.x, w01, fmaf(q0.y, w11, fmaf(q0.z, w21, fmaf(q0.w, w31, bb1))));
                    a0 += fmaxf(h0.x + e00, 0.f);
                    a1 += fmaxf(h0.y + e01, 0.f);
                }
                float2 hd = *(const float2*)(hin + (size_t)node * H + c0);
                outv.x = hd.x + (a0 + u0) + (v0 + d0);
                outv.y = hd.y + (a1 + u1) + (v1 + d1);
            }
            *(float2*)&sz[slotn][c0] = outv;
        }
        __syncthreads();

        // ---- GEMV1: t = relu(z @ W1 + b1)  (packed pairs, 3 nodes/thread)
        u64 A0 = b1lo, A1 = b1hi;
        u64 B0 = b1lo, B1 = b1hi;
        u64 C0 = b1lo, C1 = b1hi;
        #pragma unroll
        for (int k4 = 0; k4 < 16; k4++) {
            float4 z0 = *(const float4*)&sz[i0][k4 * 4];
            float4 z1 = *(const float4*)&sz[i0 + 16][k4 * 4];
            float4 z2 = *(const float4*)&sz[i0 + 32][k4 * 4];
            u64 Z0, Z1, Z2;
            ulonglong2 ww;
            #define STEP1(ZC0, ZC1, ZC2, KK) \
                DUP2(Z0, __float_as_uint(ZC0)); \
                DUP2(Z1, __float_as_uint(ZC1)); \
                DUP2(Z2, __float_as_uint(ZC2)); \
                ww = W14[(k4 * 4 + KK) * 16 + jgrp]; \
                FMA2(A0, Z0, ww.x, A0); FMA2(A1, Z0, ww.y, A1); \
                FMA2(B0, Z1, ww.x, B0); FMA2(B1, Z1, ww.y, B1); \
                FMA2(C0, Z2, ww.x, C0); FMA2(C1, Z2, ww.y, C1);
            STEP1(z0.x, z1.x, z2.x, 0)
            STEP1(z0.y, z1.y, z2.y, 1)
            STEP1(z0.z, z1.z, z2.z, 2)
            STEP1(z0.w, z1.w, z2.w, 3)
            #undef STEP1
        }
        __syncthreads();
        {
            unsigned lo, hi;
            UNPK2(lo, hi, A0);
            *(float2*)&sz[i0][jgrp * 4] =
                make_float2(fmaxf(__uint_as_float(lo), 0.f), fmaxf(__uint_as_float(hi), 0.f));
            UNPK2(lo, hi, A1);
            *(float2*)&sz[i0][jgrp * 4 + 2] =
                make_float2(fmaxf(__uint_as_float(lo), 0.f), fmaxf(__uint_as_float(hi), 0.f));
            UNPK2(lo, hi, B0);
            *(float2*)&sz[i0 + 16][jgrp * 4] =
                make_float2(fmaxf(__uint_as_float(lo), 0.f), fmaxf(__uint_as_float(hi), 0.f));
            UNPK2(lo, hi, B1);
            *(float2*)&sz[i0 + 16][jgrp * 4 + 2] =
                make_float2(fmaxf(__uint_as_float(lo), 0.f), fmaxf(__uint_as_float(hi), 0.f));
            UNPK2(lo, hi, C0);
            *(float2*)&sz[i0 + 32][jgrp * 4] =
                make_float2(fmaxf(__uint_as_float(lo), 0.f), fmaxf(__uint_as_float(hi), 0.f));
            UNPK2(lo, hi, C1);
            *(float2*)&sz[i0 + 32][jgrp * 4 + 2] =
                make_float2(fmaxf(__uint_as_float(lo), 0.f), fmaxf(__uint_as_float(hi), 0.f));
        }
        __syncthreads();
        // ---- GEMV2: h = relu(t @ W2 + b2)
        u64 D0 = b2lo, D1 = b2hi;
        u64 E0 = b2lo, E1 = b2hi;
        u64 F0 = b2lo, F1 = b2hi;
        #pragma unroll
        for (int k4 = 0; k4 < 16; k4++) {
            float4 z0 = *(const float4*)&sz[i0][k4 * 4];
            float4 z1 = *(const float4*)&sz[i0 + 16][k4 * 4];
            float4 z2 = *(const float4*)&sz[i0 + 32][k4 * 4];
            u64 Z0, Z1, Z2;
            ulonglong2 ww;
            #define STEP2(ZC0, ZC1, ZC2, KK) \
                DUP2(Z0, __float_as_uint(ZC0)); \
                DUP2(Z1, __float_as_uint(ZC1)); \
                DUP2(Z2, __float_as_uint(ZC2)); \
                ww = W24[(k4 * 4 + KK) * 16 + jgrp]; \
                FMA2(D0, Z0, ww.x, D0); FMA2(D1, Z0, ww.y, D1); \
                FMA2(E0, Z1, ww.x, E0); FMA2(E1, Z1, ww.y, E1); \
                FMA2(F0, Z2, ww.x, F0); FMA2(F1, Z2, ww.y, F1);
            STEP2(z0.x, z1.x, z2.x, 0)
            STEP2(z0.y, z1.y, z2.y, 1)
            STEP2(z0.z, z1.z, z2.z, 2)
            STEP2(z0.w, z1.w, z2.w, 3)
            #undef STEP2
        }
        float r00, r01, r02, r03, r10, r11, r12, r13, r20, r21, r22, r23;
        {
            unsigned lo, hi;
            UNPK2(lo, hi, D0); r00 = fmaxf(__uint_as_float(lo), 0.f); r01 = fmaxf(__uint_as_float(hi), 0.f);
            UNPK2(lo, hi, D1); r02 = fmaxf(__uint_as_float(lo), 0.f); r03 = fmaxf(__uint_as_float(hi), 0.f);
            UNPK2(lo, hi, E0); r10 = fmaxf(__uint_as_float(lo), 0.f); r11 = fmaxf(__uint_as_float(hi), 0.f);
            UNPK2(lo, hi, E1); r12 = fmaxf(__uint_as_float(lo), 0.f); r13 = fmaxf(__uint_as_float(hi), 0.f);
            UNPK2(lo, hi, F0); r20 = fmaxf(__uint_as_float(lo), 0.f); r21 = fmaxf(__uint_as_float(hi), 0.f);
            UNPK2(lo, hi, F1); r22 = fmaxf(__uint_as_float(lo), 0.f); r23 = fmaxf(__uint_as_float(hi), 0.f);
        }
        int n0 = base + i0, n1 = base + i0 + 16, n2 = base + i0 + 32;
        if (do_pool) {
            if (n0 < n) {
                int g = __ldg(&batch[n0]);
                float* dstp = g_sums + (size_t)g * H + jgrp * 4;
                atomicAdd(dstp + 0, r00); atomicAdd(dstp + 1, r01);
                atomicAdd(dstp + 2, r02); atomicAdd(dstp + 3, r03);
            }
            if (n1 < n) {
                int g = __ldg(&batch[n1]);
                float* dstp = g_sums + (size_t)g * H + jgrp * 4;
                atomicAdd(dstp + 0, r10); atomicAdd(dstp + 1, r11);
                atomicAdd(dstp + 2, r12); atomicAdd(dstp + 3, r13);
            }
            if (n2 < n) {
                int g = __ldg(&batch[n2]);
                float* dstp = g_sums + (size_t)g * H + jgrp * 4;
                atomicAdd(dstp + 0, r20); atomicAdd(dstp + 1, r21);
                atomicAdd(dstp + 2, r22); atomicAdd(dstp + 3, r23);
            }
        } else {
            if (n0 < n) *(float4*)(hout + (size_t)n0 * H + jgrp * 4) = make_float4(r00, r01, r02, r03);
            if (n1 < n) *(float4*)(hout + (size_t)n1 * H + jgrp * 4) = make_float4(r10, r11, r12, r13);
            if (n2 < n) *(float4*)(hout + (size_t)n2 * H + jgrp * 4) = make_float4(r20, r21, r22, r23);
        }
        __syncthreads();
    }
}

// ---------------- graph node counts via binary search (batch is sorted) -----
// Also resets the layer tile counters for the next call.
__global__ void count_kernel(const int* __restrict__ batch, int n, int G) {
    int g = blockIdx.x * blockDim.x + threadIdx.x;
    if (g < 8) g_tilectr[g] = 0;
    if (g >= G) return;
    int lo = 0, hi = n;
    while (lo < hi) { int m = (lo + hi) >> 1; if (batch[m] < g) lo = m + 1; else hi = m; }
    int start = lo;
    lo = 0; hi = n;
    while (lo < hi) { int m = (lo + hi) >> 1; if (batch[m] <= g) lo = m + 1; else hi = m; }
    g_cntf[g] = (float)(lo - start);
}

// ---------------- final: mean-pool, layernorm, linear; clean g_sums ---------
__global__ void final_kernel(float* __restrict__ out,
                             const float* __restrict__ Wout, const float* __restrict__ bout,
                             int G) {
    int warp = (blockIdx.x * blockDim.x + threadIdx.x) >> 5;
    int lane = threadIdx.x & 31;
    if (warp >= G) return;
    float cnt = fmaxf(g_cntf[warp], 1.f);
    float inv = 1.f / cnt;
    int c0 = 2 * lane;
    float v0 = g_sums[warp * H + c0] * inv;
    float v1 = g_sums[warp * H + c0 + 1] * inv;
    g_sums[warp * H + c0] = 0.f;          // clean for next call
    g_sums[warp * H + c0 + 1] = 0.f;
    float sum = v0 + v1;
    #pragma unroll
    for (int d = 16; d > 0; d >>= 1) sum += __shfl_xor_sync(0xffffffffu, sum, d);
    float mu = sum * (1.f / 64.f);
    float d0 = v0 - mu, d1 = v1 - mu;
    float var = d0 * d0 + d1 * d1;
    #pragma unroll
    for (int d = 16; d > 0; d >>= 1) var += __shfl_xor_sync(0xffffffffu, var, d);
    var *= (1.f / 64.f);
    float rstd = rsqrtf(var + 1e-5f);
    float y = d0 * rstd * Wout[c0] + d1 * rstd * Wout[c0 + 1];
    #pragma unroll
    for (int d = 16; d > 0; d >>= 1) y += __shfl_xor_sync(0xffffffffu, y, d);
    if (lane == 0) out[warp] = y + bout[0];
}

// ---------------- driver -----------------------------------------------------
extern "C" void kernel_launch(void* const* d_in, const int* in_sizes, int n_in,
                              void* d_out, int out_size) {
    const float* x         = (const float*)d_in[0];
    const int*   edge_index= (const int*)  d_in[1];
    const float* edge_attr = (const float*)d_in[2];
    const int*   batch     = (const int*)  d_in[3];
    const float* W_in      = (const float*)d_in[4];
    const float* b_in      = (const float*)d_in[5];
    const float* We        = (const float*)d_in[6];
    const float* be        = (const float*)d_in[7];
    const float* W1        = (const float*)d_in[8];
    const float* b1        = (const float*)d_in[9];
    const float* W2        = (const float*)d_in[10];
    const float* b2        = (const float*)d_in[11];
    const float* W_out     = (const float*)d_in[12];
    const float* b_out     = (const float*)d_in[13];
    float* out = (float*)d_out;

    int N = in_sizes[0] / 32;
    int E = in_sizes[1] / 2;
    int G = out_size;
    const int* src = edge_index;
    const int* dst = edge_index + E;

    float* ph;  cudaGetSymbolAddress((void**)&ph,  g_h);
    float* ph2; cudaGetSymbolAddress((void**)&ph2, g_h2);

    int nb = (N + 255) / 256;

    // g_cnt / g_sums / g_tilectr are zero on entry (zero-init on first call,
    // self-cleaned by fill / final / count on every call).
    hist_kernel<<<2048, 256>>>(dst, E);
    scan1_kernel<<<nb, 256>>>(N);
    scan2_kernel<<<1, 256>>>(nb, N);
    scan3_kernel<<<nb, 256>>>(N);
    fillproj_kernel<<<FILL_BLKS + PROJ_BLKS, 256>>>(src, dst, edge_attr, E,
                                                    x, W_in, b_in, N);

    int ntiles = (N + TILE_NODES - 1) / TILE_NODES;
    for (int l = 0; l < 5; ++l) {
        const float* hin = (l & 1) ? ph2 : ph;
        float* hout = (l & 1) ? ph : ph2;
        layer_kernel<<<888, 256>>>(hin, hout,
                                   We + l * 4 * 64, be + l * 64,
                                   W1 + l * 64 * 64, b1 + l * 64,
                                   W2 + l * 64 * 64, b2 + l * 64,
                                   batch, (l == 4) ? 1 : 0, N, ntiles, l);
    }

    count_kernel<<<(G + 255) / 256, 256>>>(batch, N, G);
    final_kernel<<<(G * 32 + 255) / 256, 256>>>(out, W_out, b_out, G);
}

// round 15
// speedup vs baseline: 1.0361x; 1.0361x over previous
#include <cuda_runtime.h>
#include <cstdint>

#define MAXN 100000
#define MAXE 1600000
#define MAXG 2048
#define H 64
#define NB_MAX ((MAXN + 255) / 256 + 1)

typedef unsigned long long u64;

// f32x2 packed math (Blackwell sm_103a): FFMA2 doubles fp32 FLOPs per instr.
#define FMA2(d, a, b, c) \
    asm("fma.rn.f32x2 %0, %1, %2, %3;" : "=l"(d) : "l"(a), "l"(b), "l"(c))
#define DUP2(d, s) \
    asm("mov.b64 %0, {%1, %1};" : "=l"(d) : "r"(s))
#define UNPK2(lo, hi, s) \
    asm("mov.b64 {%0, %1}, %2;" : "=r"(lo), "=r"(hi) : "l"(s))

// ---------------- scratch (device globals; start zero-initialized) ---------
__device__ float  g_h[MAXN * H];        // node features (ping)
__device__ float  g_h2[MAXN * H];       // node features (pong)
__device__ int    g_cnt[MAXN];          // in-degree histogram (self-cleaned)
__device__ int    g_off[MAXN + 1];      // CSR offsets by dst
__device__ int    g_cur[MAXN];          // running cursors for fill
__device__ int    g_bsum[NB_MAX];       // scan block sums
__device__ int    g_src[MAXE];          // CSR-ordered source node ids
__device__ float4 g_ea[MAXE];           // CSR-ordered edge attributes
__device__ float  g_sums[MAXG * H];     // graph pooling sums (self-cleaned)
__device__ float  g_cntf[MAXG];         // graph node counts
__device__ int    g_tilectr[8];         // layer tile-steal counters (self-cleaned)

// ---------------- CSR build -------------------------------------------------
__global__ void hist_kernel(const int* __restrict__ dst, int nedges) {
    for (int i = blockIdx.x * blockDim.x + threadIdx.x; i < nedges; i += gridDim.x * blockDim.x)
        atomicAdd(&g_cnt[dst[i]], 1);
}

// phase 1: block-local exclusive scan of g_cnt chunks; block totals -> g_bsum
__global__ void scan1_kernel(int n) {
    __shared__ int wsum[8];
    int tid = threadIdx.x, lane = tid & 31, w = tid >> 5;
    int i = blockIdx.x * 256 + tid;
    int v = (i < n) ? g_cnt[i] : 0;
    int x = v;
    #pragma unroll
    for (int d = 1; d < 32; d <<= 1) {
        int y = __shfl_up_sync(0xffffffffu, x, d);
        if (lane >= d) x += y;
    }
    if (lane == 31) wsum[w] = x;
    __syncthreads();
    if (w == 0 && lane < 8) {
        int sv = wsum[lane];
        #pragma unroll
        for (int d = 1; d < 8; d <<= 1) {
            int y = __shfl_up_sync(0xffu, sv, d);
            if (lane >= d) sv += y;
        }
        wsum[lane] = sv;
    }
    __syncthreads();
    int pre = (w == 0) ? 0 : wsum[w - 1];
    if (i < n) g_off[i] = pre + x - v;       // local exclusive
    if (tid == 255) g_bsum[blockIdx.x] = wsum[7];
}

// phase 2: single block exclusive-scans the nb block sums in place, total -> g_off[n]
__global__ void scan2_kernel(int nb, int n) {
    __shared__ int wsum[8];
    __shared__ int s_carry;
    int tid = threadIdx.x, lane = tid & 31, w = tid >> 5;
    if (tid == 0) s_carry = 0;
    __syncthreads();
    int nchunk = (nb + 255) >> 8;
    for (int c = 0; c < nchunk; c++) {
        int i = (c << 8) + tid;
        int v = (i < nb) ? g_bsum[i] : 0;
        int x = v;
        #pragma unroll
        for (int d = 1; d < 32; d <<= 1) {
            int y = __shfl_up_sync(0xffffffffu, x, d);
            if (lane >= d) x += y;
        }
        if (lane == 31) wsum[w] = x;
        __syncthreads();
        if (w == 0 && lane < 8) {
            int sv = wsum[lane];
            #pragma unroll
            for (int d = 1; d < 8; d <<= 1) {
                int y = __shfl_up_sync(0xffu, sv, d);
                if (lane >= d) sv += y;
            }
            wsum[lane] = sv;
        }
        __syncthreads();
        int pre = (w == 0) ? 0 : wsum[w - 1];
        int carry = s_carry;
        if (i < nb) g_bsum[i] = carry + pre + x - v;
        __syncthreads();
        if (tid == 0) s_carry = carry + wsum[7];
        __syncthreads();
    }
    if (tid == 0) g_off[n] = s_carry;
}

// phase 3: add block offsets; mirror to g_cur
__global__ void scan3_kernel(int n) {
    int i = blockIdx.x * blockDim.x + threadIdx.x;
    if (i < n) {
        int o = g_off[i] + g_bsum[i >> 8];
        g_off[i] = o;
        g_cur[i] = o;
    }
}

// Merged kernel: blocks [0, FILL_BLKS) fill CSR (and re-zero g_cnt for the
// next call); blocks [FILL_BLKS, FILL_BLKS+PROJ_BLKS) do the input projection.
#define FILL_BLKS 2048
#define PROJ_BLKS 1184
__global__ void fillproj_kernel(const int* __restrict__ src, const int* __restrict__ dst,
                                const float* __restrict__ edge_attr, int nedges,
                                const float* __restrict__ x,
                                const float* __restrict__ W, const float* __restrict__ b,
                                int n) {
    if (blockIdx.x < FILL_BLKS) {
        int i0 = blockIdx.x * blockDim.x + threadIdx.x;
        int stride = FILL_BLKS * blockDim.x;
        for (int i = i0; i < nedges; i += stride) {
            int d = dst[i];
            int p = atomicAdd(&g_cur[d], 1);
            g_src[p] = src[i];
            g_ea[p] = __ldg((const float4*)(edge_attr + (size_t)i * 4));
        }
        for (int i = i0; i < n; i += stride) g_cnt[i] = 0;   // clean for next call
        return;
    }
    // ---- input projection: h = relu(x @ W_in + b_in), x:[n,32] W:[32,64]
    __shared__ float sW[32 * 64];
    __shared__ float sb[64];
    __shared__ float sx[4][32];
    int tid = threadIdx.x;
    for (int i = tid; i < 32 * 64; i += 256) sW[i] = W[i];
    if (tid < 64) sb[tid] = b[tid];
    __syncthreads();
    int s = tid >> 6, j = tid & 63;
    int ntiles = (n + 3) >> 2;
    for (int tile = blockIdx.x - FILL_BLKS; tile < ntiles; tile += PROJ_BLKS) {
        int base = tile * 4;
        if (tid < 128) {
            int node = base + (tid >> 5);
            sx[tid >> 5][tid & 31] = (node < n) ? x[(size_t)node * 32 + (tid & 31)] : 0.f;
        }
        __syncthreads();
        float acc = sb[j];
        #pragma unroll
        for (int k = 0; k < 32; k++) acc = fmaf(sx[s][k], sW[k * 64 + j], acc);
        int node = base + s;
        if (node < n) g_h[(size_t)node * H + j] = fmaxf(acc, 0.f);
        __syncthreads();
    }
}

// ---------------- fused GINE layer: agg (into smem) + MLP + optional pool ---
// EXACT R13 kernel (measured 125us/layer; best known). The gather loop is
// frozen: every restructuring attempt (R5/R6/R8/R14) regressed. Grid is one
// resident wave (592 = 4 blocks/SM x 148) with tile stealing.
#define TILE_NODES 48
__global__ void __launch_bounds__(256) layer_kernel(
        const float* __restrict__ hin, float* __restrict__ hout,
        const float* __restrict__ We, const float* __restrict__ be,
        const float* __restrict__ W1, const float* __restrict__ b1,
        const float* __restrict__ W2, const float* __restrict__ b2,
        const int* __restrict__ batch, int do_pool,
        int n, int ntiles, int slot) {
    __shared__ float sW1[64 * 64];
    __shared__ float sW2[64 * 64];
    __shared__ float sz[TILE_NODES][64];
    __shared__ float sWe[4 * 64];
    __shared__ float sbe[64];
    __shared__ int s_tile;
    int tid = threadIdx.x;
    for (int i = tid; i < 64 * 64; i += 256) { sW1[i] = W1[i]; sW2[i] = W2[i]; }
    if (tid < 256) sWe[tid] = We[tid];
    if (tid < 64) sbe[tid] = be[tid];
    int jgrp = tid & 15;   // MLP output group: j = jgrp*4 (2 f32x2 pairs)
    int i0 = tid >> 4;     // MLP node slot 0..15 (others: i0+16, i0+32)
    int lane = tid & 31;   // agg ids
    int wid = tid >> 5;
    int c0 = lane * 2;
    const u64* b1p = (const u64*)b1;
    const u64* b2p = (const u64*)b2;
    u64 b1lo = __ldg(&b1p[jgrp * 2]), b1hi = __ldg(&b1p[jgrp * 2 + 1]);
    u64 b2lo = __ldg(&b2p[jgrp * 2]), b2hi = __ldg(&b2p[jgrp * 2 + 1]);
    __syncthreads();
    // agg weights into registers (per-lane channel pair)
    float w00 = sWe[0 * 64 + c0], w10 = sWe[1 * 64 + c0], w20 = sWe[2 * 64 + c0], w30 = sWe[3 * 64 + c0];
    float w01 = sWe[0 * 64 + c0 + 1], w11 = sWe[1 * 64 + c0 + 1], w21 = sWe[2 * 64 + c0 + 1], w31 = sWe[3 * 64 + c0 + 1];
    float bb0 = sbe[c0], bb1 = sbe[c0 + 1];
    const ulonglong2* W14 = (const ulonglong2*)sW1;
    const ulonglong2* W24 = (const ulonglong2*)sW2;

    for (;;) {
        if (tid == 0) s_tile = atomicAdd(&g_tilectr[slot], 1);
        __syncthreads();
        int tile = s_tile;
        if (tile >= ntiles) break;
        int base = tile * TILE_NODES;

        // ---- agg phase: warp `wid` aggregates slots [wid*6, wid*6+6)
        #pragma unroll
        for (int q = 0; q < 6; q++) {
            int slotn = wid * 6 + q;
            int node = base + slotn;
            float2 outv = make_float2(0.f, 0.f);
            if (node < n) {
                int s = g_off[node], e = g_off[node + 1];
                float a0 = 0.f, a1 = 0.f, d0 = 0.f, d1 = 0.f;
                float u0 = 0.f, u1 = 0.f, v0 = 0.f, v1 = 0.f;
                int p = s;
                for (; p + 4 <= e; p += 4) {
                    int s0 = __ldg(&g_src[p]);
                    int s1 = __ldg(&g_src[p + 1]);
                    int s2 = __ldg(&g_src[p + 2]);
                    int s3 = __ldg(&g_src[p + 3]);
                    float4 q0 = __ldg(&g_ea[p]);
                    float4 q1 = __ldg(&g_ea[p + 1]);
                    float4 q2 = __ldg(&g_ea[p + 2]);
                    float4 q3 = __ldg(&g_ea[p + 3]);
                    float2 h0 = __ldg((const float2*)(hin + (size_t)s0 * H + c0));
                    float2 h1 = __ldg((const float2*)(hin + (size_t)s1 * H + c0));
                    float2 h2 = __ldg((const float2*)(hin + (size_t)s2 * H + c0));
                    float2 h3 = __ldg((const float2*)(hin + (size_t)s3 * H + c0));
                    float e00 = fmaf(q0.x, w00, fmaf(q0.y, w10, fmaf(q0.z, w20, fmaf(q0.w, w30, bb0))));
                    float e01 = fmaf(q0.x, w01, fmaf(q0.y, w11, fmaf(q0.z, w21, fmaf(q0.w, w31, bb1))));
                    float e10 = fmaf(q1.x, w00, fmaf(q1.y, w10, fmaf(q1.z, w20, fmaf(q1.w, w30, bb0))));
                    float e11 = fmaf(q1.x, w01, fmaf(q1.y, w11, fmaf(q1.z, w21, fmaf(q1.w, w31, bb1))));
                    float e20 = fmaf(q2.x, w00, fmaf(q2.y, w10, fmaf(q2.z, w20, fmaf(q2.w, w30, bb0))));
                    float e21 = fmaf(q2.x, w01, fmaf(q2.y, w11, fmaf(q2.z, w21, fmaf(q2.w, w31, bb1))));
                    float e30 = fmaf(q3.x, w00, fmaf(q3.y, w10, fmaf(q3.z, w20, fmaf(q3.w, w30, bb0))));
                    float e31 = fmaf(q3.x, w01, fmaf(q3.y, w11, fmaf(q3.z, w21, fmaf(q3.w, w31, bb1))));
                    a0 += fmaxf(h0.x + e00, 0.f);  a1 += fmaxf(h0.y + e01, 0.f);
                    u0 += fmaxf(h1.x + e10, 0.f);  u1 += fmaxf(h1.y + e11, 0.f);
                    v0 += fmaxf(h2.x + e20, 0.f);  v1 += fmaxf(h2.y + e21, 0.f);
                    d0 += fmaxf(h3.x + e30, 0.f);  d1 += fmaxf(h3.y + e31, 0.f);
                }
                for (; p < e; ++p) {
                    int s0 = __ldg(&g_src[p]);
                    float4 q0 = __ldg(&g_ea[p]);
                    float2 h0 = __ldg((const float2*)(hin + (size_t)s0 * H + c0));
                    float e00 = fmaf(q0.x, w00, fmaf(q0.y, w10, fmaf(q0.z, w20, fmaf(q0.w, w30, bb0))));
                    float e01 = fmaf(q0.x, w01, fmaf(q0.y, w11, fmaf(q0.z, w21, fmaf(q0.w, w31, bb1))));
                    a0 += fmaxf(h0.x + e00, 0.f);
                    a1 += fmaxf(h0.y + e01, 0.f);
                }
                float2 hd = *(const float2*)(hin + (size_t)node * H + c0);
                outv.x = hd.x + (a0 + u0) + (v0 + d0);
                outv.y = hd.y + (a1 + u1) + (v1 + d1);
            }
            *(float2*)&sz[slotn][c0] = outv;
        }
        __syncthreads();

        // ---- GEMV1: t = relu(z @ W1 + b1)  (packed pairs, 3 nodes/thread)
        u64 A0 = b1lo, A1 = b1hi;
        u64 B0 = b1lo, B1 = b1hi;
        u64 C0 = b1lo, C1 = b1hi;
        #pragma unroll
        for (int k4 = 0; k4 < 16; k4++) {
            float4 z0 = *(const float4*)&sz[i0][k4 * 4];
            float4 z1 = *(const float4*)&sz[i0 + 16][k4 * 4];
            float4 z2 = *(const float4*)&sz[i0 + 32][k4 * 4];
            u64 Z0, Z1, Z2;
            ulonglong2 ww;
            #define STEP1(ZC0, ZC1, ZC2, KK) \
                DUP2(Z0, __float_as_uint(ZC0)); \
                DUP2(Z1, __float_as_uint(ZC1)); \
                DUP2(Z2, __float_as_uint(ZC2)); \
                ww = W14[(k4 * 4 + KK) * 16 + jgrp]; \
                FMA2(A0, Z0, ww.x, A0); FMA2(A1, Z0, ww.y, A1); \
                FMA2(B0, Z1, ww.x, B0); FMA2(B1, Z1, ww.y, B1); \
                FMA2(C0, Z2, ww.x, C0); FMA2(C1, Z2, ww.y, C1);
            STEP1(z0.x, z1.x, z2.x, 0)
            STEP1(z0.y, z1.y, z2.y, 1)
            STEP1(z0.z, z1.z, z2.z, 2)
            STEP1(z0.w, z1.w, z2.w, 3)
            #undef STEP1
        }
        __syncthreads();
        {
            unsigned lo, hi;
            UNPK2(lo, hi, A0);
            *(float2*)&sz[i0][jgrp * 4] =
                make_float2(fmaxf(__uint_as_float(lo), 0.f), fmaxf(__uint_as_float(hi), 0.f));
            UNPK2(lo, hi, A1);
            *(float2*)&sz[i0][jgrp * 4 + 2] =
                make_float2(fmaxf(__uint_as_float(lo), 0.f), fmaxf(__uint_as_float(hi), 0.f));
            UNPK2(lo, hi, B0);
            *(float2*)&sz[i0 + 16][jgrp * 4] =
                make_float2(fmaxf(__uint_as_float(lo), 0.f), fmaxf(__uint_as_float(hi), 0.f));
            UNPK2(lo, hi, B1);
            *(float2*)&sz[i0 + 16][jgrp * 4 + 2] =
                make_float2(fmaxf(__uint_as_float(lo), 0.f), fmaxf(__uint_as_float(hi), 0.f));
            UNPK2(lo, hi, C0);
            *(float2*)&sz[i0 + 32][jgrp * 4] =
                make_float2(fmaxf(__uint_as_float(lo), 0.f), fmaxf(__uint_as_float(hi), 0.f));
            UNPK2(lo, hi, C1);
            *(float2*)&sz[i0 + 32][jgrp * 4 + 2] =
                make_float2(fmaxf(__uint_as_float(lo), 0.f), fmaxf(__uint_as_float(hi), 0.f));
        }
        __syncthreads();
        // ---- GEMV2: h = relu(t @ W2 + b2)
        u64 D0 = b2lo, D1 = b2hi;
        u64 E0 = b2lo, E1 = b2hi;
        u64 F0 = b2lo, F1 = b2hi;
        #pragma unroll
        for (int k4 = 0; k4 < 16; k4++) {
            float4 z0 = *(const float4*)&sz[i0][k4 * 4];
            float4 z1 = *(const float4*)&sz[i0 + 16][k4 * 4];
            float4 z2 = *(const float4*)&sz[i0 + 32][k4 * 4];
            u64 Z0, Z1, Z2;
            ulonglong2 ww;
            #define STEP2(ZC0, ZC1, ZC2, KK) \
                DUP2(Z0, __float_as_uint(ZC0)); \
                DUP2(Z1, __float_as_uint(ZC1)); \
                DUP2(Z2, __float_as_uint(ZC2)); \
                ww = W24[(k4 * 4 + KK) * 16 + jgrp]; \
                FMA2(D0, Z0, ww.x, D0); FMA2(D1, Z0, ww.y, D1); \
                FMA2(E0, Z1, ww.x, E0); FMA2(E1, Z1, ww.y, E1); \
                FMA2(F0, Z2, ww.x, F0); FMA2(F1, Z2, ww.y, F1);
            STEP2(z0.x, z1.x, z2.x, 0)
            STEP2(z0.y, z1.y, z2.y, 1)
            STEP2(z0.z, z1.z, z2.z, 2)
            STEP2(z0.w, z1.w, z2.w, 3)
            #undef STEP2
        }
        float r00, r01, r02, r03, r10, r11, r12, r13, r20, r21, r22, r23;
        {
            unsigned lo, hi;
            UNPK2(lo, hi, D0); r00 = fmaxf(__uint_as_float(lo), 0.f); r01 = fmaxf(__uint_as_float(hi), 0.f);
            UNPK2(lo, hi, D1); r02 = fmaxf(__uint_as_float(lo), 0.f); r03 = fmaxf(__uint_as_float(hi), 0.f);
            UNPK2(lo, hi, E0); r10 = fmaxf(__uint_as_float(lo), 0.f); r11 = fmaxf(__uint_as_float(hi), 0.f);
            UNPK2(lo, hi, E1); r12 = fmaxf(__uint_as_float(lo), 0.f); r13 = fmaxf(__uint_as_float(hi), 0.f);
            UNPK2(lo, hi, F0); r20 = fmaxf(__uint_as_float(lo), 0.f); r21 = fmaxf(__uint_as_float(hi), 0.f);
            UNPK2(lo, hi, F1); r22 = fmaxf(__uint_as_float(lo), 0.f); r23 = fmaxf(__uint_as_float(hi), 0.f);
        }
        int n0 = base + i0, n1 = base + i0 + 16, n2 = base + i0 + 32;
        if (do_pool) {
            if (n0 < n) {
                int g = __ldg(&batch[n0]);
                float* dstp = g_sums + (size_t)g * H + jgrp * 4;
                atomicAdd(dstp + 0, r00); atomicAdd(dstp + 1, r01);
                atomicAdd(dstp + 2, r02); atomicAdd(dstp + 3, r03);
            }
            if (n1 < n) {
                int g = __ldg(&batch[n1]);
                float* dstp = g_sums + (size_t)g * H + jgrp * 4;
                atomicAdd(dstp + 0, r10); atomicAdd(dstp + 1, r11);
                atomicAdd(dstp + 2, r12); atomicAdd(dstp + 3, r13);
            }
            if (n2 < n) {
                int g = __ldg(&batch[n2]);
                float* dstp = g_sums + (size_t)g * H + jgrp * 4;
                atomicAdd(dstp + 0, r20); atomicAdd(dstp + 1, r21);
                atomicAdd(dstp + 2, r22); atomicAdd(dstp + 3, r23);
            }
        } else {
            if (n0 < n) *(float4*)(hout + (size_t)n0 * H + jgrp * 4) = make_float4(r00, r01, r02, r03);
            if (n1 < n) *(float4*)(hout + (size_t)n1 * H + jgrp * 4) = make_float4(r10, r11, r12, r13);
            if (n2 < n) *(float4*)(hout + (size_t)n2 * H + jgrp * 4) = make_float4(r20, r21, r22, r23);
        }
        __syncthreads();
    }
}

// ---------------- graph node counts via binary search (batch is sorted) -----
// Also resets the layer tile counters for the next call.
__global__ void count_kernel(const int* __restrict__ batch, int n, int G) {
    int g = blockIdx.x * blockDim.x + threadIdx.x;
    if (g < 8) g_tilectr[g] = 0;
    if (g >= G) return;
    int lo = 0, hi = n;
    while (lo < hi) { int m = (lo + hi) >> 1; if (batch[m] < g) lo = m + 1; else hi = m; }
    int start = lo;
    lo = 0; hi = n;
    while (lo < hi) { int m = (lo + hi) >> 1; if (batch[m] <= g) lo = m + 1; else hi = m; }
    g_cntf[g] = (float)(lo - start);
}

// ---------------- final: mean-pool, layernorm, linear; clean g_sums ---------
__global__ void final_kernel(float* __restrict__ out,
                             const float* __restrict__ Wout, const float* __restrict__ bout,
                             int G) {
    int warp = (blockIdx.x * blockDim.x + threadIdx.x) >> 5;
    int lane = threadIdx.x & 31;
    if (warp >= G) return;
    float cnt = fmaxf(g_cntf[warp], 1.f);
    float inv = 1.f / cnt;
    int c0 = 2 * lane;
    float v0 = g_sums[warp * H + c0] * inv;
    float v1 = g_sums[warp * H + c0 + 1] * inv;
    g_sums[warp * H + c0] = 0.f;          // clean for next call
    g_sums[warp * H + c0 + 1] = 0.f;
    float sum = v0 + v1;
    #pragma unroll
    for (int d = 16; d > 0; d >>= 1) sum += __shfl_xor_sync(0xffffffffu, sum, d);
    float mu = sum * (1.f / 64.f);
    float d0 = v0 - mu, d1 = v1 - mu;
    float var = d0 * d0 + d1 * d1;
    #pragma unroll
    for (int d = 16; d > 0; d >>= 1) var += __shfl_xor_sync(0xffffffffu, var, d);
    var *= (1.f / 64.f);
    float rstd = rsqrtf(var + 1e-5f);
    float y = d0 * rstd * Wout[c0] + d1 * rstd * Wout[c0 + 1];
    #pragma unroll
    for (int d = 16; d > 0; d >>= 1) y += __shfl_xor_sync(0xffffffffu, y, d);
    if (lane == 0) out[warp] = y + bout[0];
}

// ---------------- driver -----------------------------------------------------
extern "C" void kernel_launch(void* const* d_in, const int* in_sizes, int n_in,
                              void* d_out, int out_size) {
    const float* x         = (const float*)d_in[0];
    const int*   edge_index= (const int*)  d_in[1];
    const float* edge_attr = (const float*)d_in[2];
    const int*   batch     = (const int*)  d_in[3];
    const float* W_in      = (const float*)d_in[4];
    const float* b_in      = (const float*)d_in[5];
    const float* We        = (const float*)d_in[6];
    const float* be        = (const float*)d_in[7];
    const float* W1        = (const float*)d_in[8];
    const float* b1        = (const float*)d_in[9];
    const float* W2        = (const float*)d_in[10];
    const float* b2        = (const float*)d_in[11];
    const float* W_out     = (const float*)d_in[12];
    const float* b_out     = (const float*)d_in[13];
    float* out = (float*)d_out;

    int N = in_sizes[0] / 32;
    int E = in_sizes[1] / 2;
    int G = out_size;
    const int* src = edge_index;
    const int* dst = edge_index + E;

    float* ph;  cudaGetSymbolAddress((void**)&ph,  g_h);
    float* ph2; cudaGetSymbolAddress((void**)&ph2, g_h2);

    int nb = (N + 255) / 256;

    // g_cnt / g_sums / g_tilectr are zero on entry (zero-init on first call,
    // self-cleaned by fill / final / count on every call).
    hist_kernel<<<2048, 256>>>(dst, E);
    scan1_kernel<<<nb, 256>>>(N);
    scan2_kernel<<<1, 256>>>(nb, N);
    scan3_kernel<<<nb, 256>>>(N);
    fillproj_kernel<<<FILL_BLKS + PROJ_BLKS, 256>>>(src, dst, edge_attr, E,
                                                    x, W_in, b_in, N);

    int ntiles = (N + TILE_NODES - 1) / TILE_NODES;
    for (int l = 0; l < 5; ++l) {
        const float* hin = (l & 1) ? ph2 : ph;
        float* hout = (l & 1) ? ph : ph2;
        layer_kernel<<<592, 256>>>(hin, hout,
                                   We + l * 4 * 64, be + l * 64,
                                   W1 + l * 64 * 64, b1 + l * 64,
                                   W2 + l * 64 * 64, b2 + l * 64,
                                   batch, (l == 4) ? 1 : 0, N, ntiles, l);
    }

    count_kernel<<<(G + 255) / 256, 256>>>(batch, N, G);
    final_kernel<<<(G * 32 + 255) / 256, 256>>>(out, W_out, b_out, G);
}

// round 16
// speedup vs baseline: 1.0588x; 1.0218x over previous
#include <cuda_runtime.h>
#include <cstdint>

#define MAXN 100000
#define MAXE 1600000
#define MAXG 2048
#define H 64
#define NB_MAX ((MAXN + 255) / 256 + 1)

typedef unsigned long long u64;

// f32x2 packed math (Blackwell sm_103a): FFMA2 doubles fp32 FLOPs per instr.
#define FMA2(d, a, b, c) \
    asm("fma.rn.f32x2 %0, %1, %2, %3;" : "=l"(d) : "l"(a), "l"(b), "l"(c))
#define DUP2(d, s) \
    asm("mov.b64 %0, {%1, %1};" : "=l"(d) : "r"(s))
#define UNPK2(lo, hi, s) \
    asm("mov.b64 {%0, %1}, %2;" : "=r"(lo), "=r"(hi) : "l"(s))

// ---------------- scratch (device globals; start zero-initialized) ---------
__device__ float  g_h[MAXN * H];        // node features (ping)
__device__ float  g_h2[MAXN * H];       // node features (pong)
__device__ int    g_cnt[MAXN];          // in-degree histogram (self-cleaned)
__device__ int    g_off[MAXN + 1];      // CSR offsets by dst
__device__ int    g_cur[MAXN];          // running cursors for fill
__device__ int    g_bsum[NB_MAX];       // scan block sums
__device__ int    g_src[MAXE];          // CSR-ordered source node ids
__device__ float4 g_ea[MAXE];           // CSR-ordered edge attributes
__device__ float  g_sums[MAXG * H];     // graph pooling sums (self-cleaned)
__device__ int    g_tilectr[8];         // layer tile-steal counters (self-cleaned)

// ---------------- CSR build -------------------------------------------------
__global__ void hist_kernel(const int* __restrict__ dst, int nedges) {
    for (int i = blockIdx.x * blockDim.x + threadIdx.x; i < nedges; i += gridDim.x * blockDim.x)
        atomicAdd(&g_cnt[dst[i]], 1);
}

// phase 1: block-local exclusive scan of g_cnt chunks; block totals -> g_bsum
__global__ void scan1_kernel(int n) {
    __shared__ int wsum[8];
    int tid = threadIdx.x, lane = tid & 31, w = tid >> 5;
    int i = blockIdx.x * 256 + tid;
    int v = (i < n) ? g_cnt[i] : 0;
    int x = v;
    #pragma unroll
    for (int d = 1; d < 32; d <<= 1) {
        int y = __shfl_up_sync(0xffffffffu, x, d);
        if (lane >= d) x += y;
    }
    if (lane == 31) wsum[w] = x;
    __syncthreads();
    if (w == 0 && lane < 8) {
        int sv = wsum[lane];
        #pragma unroll
        for (int d = 1; d < 8; d <<= 1) {
            int y = __shfl_up_sync(0xffu, sv, d);
            if (lane >= d) sv += y;
        }
        wsum[lane] = sv;
    }
    __syncthreads();
    int pre = (w == 0) ? 0 : wsum[w - 1];
    if (i < n) g_off[i] = pre + x - v;       // local exclusive
    if (tid == 255) g_bsum[blockIdx.x] = wsum[7];
}

// phase 2: single block exclusive-scans the nb block sums in place, total -> g_off[n]
__global__ void scan2_kernel(int nb, int n) {
    __shared__ int wsum[8];
    __shared__ int s_carry;
    int tid = threadIdx.x, lane = tid & 31, w = tid >> 5;
    if (tid == 0) s_carry = 0;
    __syncthreads();
    int nchunk = (nb + 255) >> 8;
    for (int c = 0; c < nchunk; c++) {
        int i = (c << 8) + tid;
        int v = (i < nb) ? g_bsum[i] : 0;
        int x = v;
        #pragma unroll
        for (int d = 1; d < 32; d <<= 1) {
            int y = __shfl_up_sync(0xffffffffu, x, d);
            if (lane >= d) x += y;
        }
        if (lane == 31) wsum[w] = x;
        __syncthreads();
        if (w == 0 && lane < 8) {
            int sv = wsum[lane];
            #pragma unroll
            for (int d = 1; d < 8; d <<= 1) {
                int y = __shfl_up_sync(0xffu, sv, d);
                if (lane >= d) sv += y;
            }
            wsum[lane] = sv;
        }
        __syncthreads();
        int pre = (w == 0) ? 0 : wsum[w - 1];
        int carry = s_carry;
        if (i < nb) g_bsum[i] = carry + pre + x - v;
        __syncthreads();
        if (tid == 0) s_carry = carry + wsum[7];
        __syncthreads();
    }
    if (tid == 0) g_off[n] = s_carry;
}

// phase 3: add block offsets; mirror to g_cur
__global__ void scan3_kernel(int n) {
    int i = blockIdx.x * blockDim.x + threadIdx.x;
    if (i < n) {
        int o = g_off[i] + g_bsum[i >> 8];
        g_off[i] = o;
        g_cur[i] = o;
    }
}

// Merged kernel: blocks [0, FILL_BLKS) fill CSR (and re-zero g_cnt for the
// next call); blocks [FILL_BLKS, FILL_BLKS+PROJ_BLKS) do the input projection.
#define FILL_BLKS 2048
#define PROJ_BLKS 1184
__global__ void fillproj_kernel(const int* __restrict__ src, const int* __restrict__ dst,
                                const float* __restrict__ edge_attr, int nedges,
                                const float* __restrict__ x,
                                const float* __restrict__ W, const float* __restrict__ b,
                                int n) {
    if (blockIdx.x < FILL_BLKS) {
        int i0 = blockIdx.x * blockDim.x + threadIdx.x;
        int stride = FILL_BLKS * blockDim.x;
        for (int i = i0; i < nedges; i += stride) {
            int d = dst[i];
            int p = atomicAdd(&g_cur[d], 1);
            g_src[p] = src[i];
            g_ea[p] = __ldg((const float4*)(edge_attr + (size_t)i * 4));
        }
        for (int i = i0; i < n; i += stride) g_cnt[i] = 0;   // clean for next call
        return;
    }
    // ---- input projection: h = relu(x @ W_in + b_in), x:[n,32] W:[32,64]
    __shared__ float sW[32 * 64];
    __shared__ float sb[64];
    __shared__ float sx[4][32];
    int tid = threadIdx.x;
    for (int i = tid; i < 32 * 64; i += 256) sW[i] = W[i];
    if (tid < 64) sb[tid] = b[tid];
    __syncthreads();
    int s = tid >> 6, j = tid & 63;
    int ntiles = (n + 3) >> 2;
    for (int tile = blockIdx.x - FILL_BLKS; tile < ntiles; tile += PROJ_BLKS) {
        int base = tile * 4;
        if (tid < 128) {
            int node = base + (tid >> 5);
            sx[tid >> 5][tid & 31] = (node < n) ? x[(size_t)node * 32 + (tid & 31)] : 0.f;
        }
        __syncthreads();
        float acc = sb[j];
        #pragma unroll
        for (int k = 0; k < 32; k++) acc = fmaf(sx[s][k], sW[k * 64 + j], acc);
        int node = base + s;
        if (node < n) g_h[(size_t)node * H + j] = fmaxf(acc, 0.f);
        __syncthreads();
    }
}

// ---------------- fused GINE layer: agg (into smem) + MLP + optional pool ---
// EXACT R13 kernel (measured 125us/layer; best known). The gather loop is
// frozen: every restructuring attempt (R5/R6/R8/R14) regressed. Grid 888
// (R13-measured best) with tile stealing.
#define TILE_NODES 48
__global__ void __launch_bounds__(256) layer_kernel(
        const float* __restrict__ hin, float* __restrict__ hout,
        const float* __restrict__ We, const float* __restrict__ be,
        const float* __restrict__ W1, const float* __restrict__ b1,
        const float* __restrict__ W2, const float* __restrict__ b2,
        const int* __restrict__ batch, int do_pool,
        int n, int ntiles, int slot) {
    __shared__ float sW1[64 * 64];
    __shared__ float sW2[64 * 64];
    __shared__ float sz[TILE_NODES][64];
    __shared__ float sWe[4 * 64];
    __shared__ float sbe[64];
    __shared__ int s_tile;
    int tid = threadIdx.x;
    for (int i = tid; i < 64 * 64; i += 256) { sW1[i] = W1[i]; sW2[i] = W2[i]; }
    if (tid < 256) sWe[tid] = We[tid];
    if (tid < 64) sbe[tid] = be[tid];
    int jgrp = tid & 15;   // MLP output group: j = jgrp*4 (2 f32x2 pairs)
    int i0 = tid >> 4;     // MLP node slot 0..15 (others: i0+16, i0+32)
    int lane = tid & 31;   // agg ids
    int wid = tid >> 5;
    int c0 = lane * 2;
    const u64* b1p = (const u64*)b1;
    const u64* b2p = (const u64*)b2;
    u64 b1lo = __ldg(&b1p[jgrp * 2]), b1hi = __ldg(&b1p[jgrp * 2 + 1]);
    u64 b2lo = __ldg(&b2p[jgrp * 2]), b2hi = __ldg(&b2p[jgrp * 2 + 1]);
    __syncthreads();
    // agg weights into registers (per-lane channel pair)
    float w00 = sWe[0 * 64 + c0], w10 = sWe[1 * 64 + c0], w20 = sWe[2 * 64 + c0], w30 = sWe[3 * 64 + c0];
    float w01 = sWe[0 * 64 + c0 + 1], w11 = sWe[1 * 64 + c0 + 1], w21 = sWe[2 * 64 + c0 + 1], w31 = sWe[3 * 64 + c0 + 1];
    float bb0 = sbe[c0], bb1 = sbe[c0 + 1];
    const ulonglong2* W14 = (const ulonglong2*)sW1;
    const ulonglong2* W24 = (const ulonglong2*)sW2;

    for (;;) {
        if (tid == 0) s_tile = atomicAdd(&g_tilectr[slot], 1);
        __syncthreads();
        int tile = s_tile;
        if (tile >= ntiles) break;
        int base = tile * TILE_NODES;

        // ---- agg phase: warp `wid` aggregates slots [wid*6, wid*6+6)
        #pragma unroll
        for (int q = 0; q < 6; q++) {
            int slotn = wid * 6 + q;
            int node = base + slotn;
            float2 outv = make_float2(0.f, 0.f);
            if (node < n) {
                int s = g_off[node], e = g_off[node + 1];
                float a0 = 0.f, a1 = 0.f, d0 = 0.f, d1 = 0.f;
                float u0 = 0.f, u1 = 0.f, v0 = 0.f, v1 = 0.f;
                int p = s;
                for (; p + 4 <= e; p += 4) {
                    int s0 = __ldg(&g_src[p]);
                    int s1 = __ldg(&g_src[p + 1]);
                    int s2 = __ldg(&g_src[p + 2]);
                    int s3 = __ldg(&g_src[p + 3]);
                    float4 q0 = __ldg(&g_ea[p]);
                    float4 q1 = __ldg(&g_ea[p + 1]);
                    float4 q2 = __ldg(&g_ea[p + 2]);
                    float4 q3 = __ldg(&g_ea[p + 3]);
                    float2 h0 = __ldg((const float2*)(hin + (size_t)s0 * H + c0));
                    float2 h1 = __ldg((const float2*)(hin + (size_t)s1 * H + c0));
                    float2 h2 = __ldg((const float2*)(hin + (size_t)s2 * H + c0));
                    float2 h3 = __ldg((const float2*)(hin + (size_t)s3 * H + c0));
                    float e00 = fmaf(q0.x, w00, fmaf(q0.y, w10, fmaf(q0.z, w20, fmaf(q0.w, w30, bb0))));
                    float e01 = fmaf(q0.x, w01, fmaf(q0.y, w11, fmaf(q0.z, w21, fmaf(q0.w, w31, bb1))));
                    float e10 = fmaf(q1.x, w00, fmaf(q1.y, w10, fmaf(q1.z, w20, fmaf(q1.w, w30, bb0))));
                    float e11 = fmaf(q1.x, w01, fmaf(q1.y, w11, fmaf(q1.z, w21, fmaf(q1.w, w31, bb1))));
                    float e20 = fmaf(q2.x, w00, fmaf(q2.y, w10, fmaf(q2.z, w20, fmaf(q2.w, w30, bb0))));
                    float e21 = fmaf(q2.x, w01, fmaf(q2.y, w11, fmaf(q2.z, w21, fmaf(q2.w, w31, bb1))));
                    float e30 = fmaf(q3.x, w00, fmaf(q3.y, w10, fmaf(q3.z, w20, fmaf(q3.w, w30, bb0))));
                    float e31 = fmaf(q3.x, w01, fmaf(q3.y, w11, fmaf(q3.z, w21, fmaf(q3.w, w31, bb1))));
                    a0 += fmaxf(h0.x + e00, 0.f);  a1 += fmaxf(h0.y + e01, 0.f);
                    u0 += fmaxf(h1.x + e10, 0.f);  u1 += fmaxf(h1.y + e11, 0.f);
                    v0 += fmaxf(h2.x + e20, 0.f);  v1 += fmaxf(h2.y + e21, 0.f);
                    d0 += fmaxf(h3.x + e30, 0.f);  d1 += fmaxf(h3.y + e31, 0.f);
                }
                for (; p < e; ++p) {
                    int s0 = __ldg(&g_src[p]);
                    float4 q0 = __ldg(&g_ea[p]);
                    float2 h0 = __ldg((const float2*)(hin + (size_t)s0 * H + c0));
                    float e00 = fmaf(q0.x, w00, fmaf(q0.y, w10, fmaf(q0.z, w20, fmaf(q0.w, w30, bb0))));
                    float e01 = fmaf(q0.x, w01, fmaf(q0.y, w11, fmaf(q0.z, w21, fmaf(q0.w, w31, bb1))));
                    a0 += fmaxf(h0.x + e00, 0.f);
                    a1 += fmaxf(h0.y + e01, 0.f);
                }
                float2 hd = *(const float2*)(hin + (size_t)node * H + c0);
                outv.x = hd.x + (a0 + u0) + (v0 + d0);
                outv.y = hd.y + (a1 + u1) + (v1 + d1);
            }
            *(float2*)&sz[slotn][c0] = outv;
        }
        __syncthreads();

        // ---- GEMV1: t = relu(z @ W1 + b1)  (packed pairs, 3 nodes/thread)
        u64 A0 = b1lo, A1 = b1hi;
        u64 B0 = b1lo, B1 = b1hi;
        u64 C0 = b1lo, C1 = b1hi;
        #pragma unroll
        for (int k4 = 0; k4 < 16; k4++) {
            float4 z0 = *(const float4*)&sz[i0][k4 * 4];
            float4 z1 = *(const float4*)&sz[i0 + 16][k4 * 4];
            float4 z2 = *(const float4*)&sz[i0 + 32][k4 * 4];
            u64 Z0, Z1, Z2;
            ulonglong2 ww;
            #define STEP1(ZC0, ZC1, ZC2, KK) \
                DUP2(Z0, __float_as_uint(ZC0)); \
                DUP2(Z1, __float_as_uint(ZC1)); \
                DUP2(Z2, __float_as_uint(ZC2)); \
                ww = W14[(k4 * 4 + KK) * 16 + jgrp]; \
                FMA2(A0, Z0, ww.x, A0); FMA2(A1, Z0, ww.y, A1); \
                FMA2(B0, Z1, ww.x, B0); FMA2(B1, Z1, ww.y, B1); \
                FMA2(C0, Z2, ww.x, C0); FMA2(C1, Z2, ww.y, C1);
            STEP1(z0.x, z1.x, z2.x, 0)
            STEP1(z0.y, z1.y, z2.y, 1)
            STEP1(z0.z, z1.z, z2.z, 2)
            STEP1(z0.w, z1.w, z2.w, 3)
            #undef STEP1
        }
        __syncthreads();
        {
            unsigned lo, hi;
            UNPK2(lo, hi, A0);
            *(float2*)&sz[i0][jgrp * 4] =
                make_float2(fmaxf(__uint_as_float(lo), 0.f), fmaxf(__uint_as_float(hi), 0.f));
            UNPK2(lo, hi, A1);
            *(float2*)&sz[i0][jgrp * 4 + 2] =
                make_float2(fmaxf(__uint_as_float(lo), 0.f), fmaxf(__uint_as_float(hi), 0.f));
            UNPK2(lo, hi, B0);
            *(float2*)&sz[i0 + 16][jgrp * 4] =
                make_float2(fmaxf(__uint_as_float(lo), 0.f), fmaxf(__uint_as_float(hi), 0.f));
            UNPK2(lo, hi, B1);
            *(float2*)&sz[i0 + 16][jgrp * 4 + 2] =
                make_float2(fmaxf(__uint_as_float(lo), 0.f), fmaxf(__uint_as_float(hi), 0.f));
            UNPK2(lo, hi, C0);
            *(float2*)&sz[i0 + 32][jgrp * 4] =
                make_float2(fmaxf(__uint_as_float(lo), 0.f), fmaxf(__uint_as_float(hi), 0.f));
            UNPK2(lo, hi, C1);
            *(float2*)&sz[i0 + 32][jgrp * 4 + 2] =
                make_float2(fmaxf(__uint_as_float(lo), 0.f), fmaxf(__uint_as_float(hi), 0.f));
        }
        __syncthreads();
        // ---- GEMV2: h = relu(t @ W2 + b2)
        u64 D0 = b2lo, D1 = b2hi;
        u64 E0 = b2lo, E1 = b2hi;
        u64 F0 = b2lo, F1 = b2hi;
        #pragma unroll
        for (int k4 = 0; k4 < 16; k4++) {
            float4 z0 = *(const float4*)&sz[i0][k4 * 4];
            float4 z1 = *(const float4*)&sz[i0 + 16][k4 * 4];
            float4 z2 = *(const float4*)&sz[i0 + 32][k4 * 4];
            u64 Z0, Z1, Z2;
            ulonglong2 ww;
            #define STEP2(ZC0, ZC1, ZC2, KK) \
                DUP2(Z0, __float_as_uint(ZC0)); \
                DUP2(Z1, __float_as_uint(ZC1)); \
                DUP2(Z2, __float_as_uint(ZC2)); \
                ww = W24[(k4 * 4 + KK) * 16 + jgrp]; \
                FMA2(D0, Z0, ww.x, D0); FMA2(D1, Z0, ww.y, D1); \
                FMA2(E0, Z1, ww.x, E0); FMA2(E1, Z1, ww.y, E1); \
                FMA2(F0, Z2, ww.x, F0); FMA2(F1, Z2, ww.y, F1);
            STEP2(z0.x, z1.x, z2.x, 0)
            STEP2(z0.y, z1.y, z2.y, 1)
            STEP2(z0.z, z1.z, z2.z, 2)
            STEP2(z0.w, z1.w, z2.w, 3)
            #undef STEP2
        }
        float r00, r01, r02, r03, r10, r11, r12, r13, r20, r21, r22, r23;
        {
            unsigned lo, hi;
            UNPK2(lo, hi, D0); r00 = fmaxf(__uint_as_float(lo), 0.f); r01 = fmaxf(__uint_as_float(hi), 0.f);
            UNPK2(lo, hi, D1); r02 = fmaxf(__uint_as_float(lo), 0.f); r03 = fmaxf(__uint_as_float(hi), 0.f);
            UNPK2(lo, hi, E0); r10 = fmaxf(__uint_as_float(lo), 0.f); r11 = fmaxf(__uint_as_float(hi), 0.f);
            UNPK2(lo, hi, E1); r12 = fmaxf(__uint_as_float(lo), 0.f); r13 = fmaxf(__uint_as_float(hi), 0.f);
            UNPK2(lo, hi, F0); r20 = fmaxf(__uint_as_float(lo), 0.f); r21 = fmaxf(__uint_as_float(hi), 0.f);
            UNPK2(lo, hi, F1); r22 = fmaxf(__uint_as_float(lo), 0.f); r23 = fmaxf(__uint_as_float(hi), 0.f);
        }
        int n0 = base + i0, n1 = base + i0 + 16, n2 = base + i0 + 32;
        if (do_pool) {
            if (n0 < n) {
                int g = __ldg(&batch[n0]);
                float* dstp = g_sums + (size_t)g * H + jgrp * 4;
                atomicAdd(dstp + 0, r00); atomicAdd(dstp + 1, r01);
                atomicAdd(dstp + 2, r02); atomicAdd(dstp + 3, r03);
            }
            if (n1 < n) {
                int g = __ldg(&batch[n1]);
                float* dstp = g_sums + (size_t)g * H + jgrp * 4;
                atomicAdd(dstp + 0, r10); atomicAdd(dstp + 1, r11);
                atomicAdd(dstp + 2, r12); atomicAdd(dstp + 3, r13);
            }
            if (n2 < n) {
                int g = __ldg(&batch[n2]);
                float* dstp = g_sums + (size_t)g * H + jgrp * 4;
                atomicAdd(dstp + 0, r20); atomicAdd(dstp + 1, r21);
                atomicAdd(dstp + 2, r22); atomicAdd(dstp + 3, r23);
            }
        } else {
            if (n0 < n) *(float4*)(hout + (size_t)n0 * H + jgrp * 4) = make_float4(r00, r01, r02, r03);
            if (n1 < n) *(float4*)(hout + (size_t)n1 * H + jgrp * 4) = make_float4(r10, r11, r12, r13);
            if (n2 < n) *(float4*)(hout + (size_t)n2 * H + jgrp * 4) = make_float4(r20, r21, r22, r23);
        }
        __syncthreads();
    }
}

// ---------------- final: count (binary search) + mean-pool + LN + linear ----
// Merged: lanes 0/1 binary-search the sorted batch array for this graph's
// node range; also resets the layer tile counters and cleans g_sums.
__global__ void final_kernel(float* __restrict__ out,
                             const int* __restrict__ batch, int n,
                             const float* __restrict__ Wout, const float* __restrict__ bout,
                             int G) {
    int gw = (blockIdx.x * blockDim.x + threadIdx.x) >> 5;
    int lane = threadIdx.x & 31;
    if (gw == 0 && lane < 8) g_tilectr[lane] = 0;   // reset for next call
    if (gw >= G) return;
    int bound = 0;
    if (lane < 2) {
        // lane 0: lower_bound(gw); lane 1: upper_bound(gw) = lower_bound(gw+1)
        int key = gw + lane;
        int lo = 0, hi = n;
        while (lo < hi) { int m = (lo + hi) >> 1; if (batch[m] < key) lo = m + 1; else hi = m; }
        bound = lo;
    }
    int start = __shfl_sync(0xffffffffu, bound, 0);
    int end   = __shfl_sync(0xffffffffu, bound, 1);
    float cnt = fmaxf((float)(end - start), 1.f);
    float inv = 1.f / cnt;
    int c0 = 2 * lane;
    float v0 = g_sums[gw * H + c0] * inv;
    float v1 = g_sums[gw * H + c0 + 1] * inv;
    g_sums[gw * H + c0] = 0.f;          // clean for next call
    g_sums[gw * H + c0 + 1] = 0.f;
    float sum = v0 + v1;
    #pragma unroll
    for (int d = 16; d > 0; d >>= 1) sum += __shfl_xor_sync(0xffffffffu, sum, d);
    float mu = sum * (1.f / 64.f);
    float d0 = v0 - mu, d1 = v1 - mu;
    float var = d0 * d0 + d1 * d1;
    #pragma unroll
    for (int d = 16; d > 0; d >>= 1) var += __shfl_xor_sync(0xffffffffu, var, d);
    var *= (1.f / 64.f);
    float rstd = rsqrtf(var + 1e-5f);
    float y = d0 * rstd * Wout[c0] + d1 * rstd * Wout[c0 + 1];
    #pragma unroll
    for (int d = 16; d > 0; d >>= 1) y += __shfl_xor_sync(0xffffffffu, y, d);
    if (lane == 0) out[gw] = y + bout[0];
}

// ---------------- driver -----------------------------------------------------
extern "C" void kernel_launch(void* const* d_in, const int* in_sizes, int n_in,
                              void* d_out, int out_size) {
    const float* x         = (const float*)d_in[0];
    const int*   edge_index= (const int*)  d_in[1];
    const float* edge_attr = (const float*)d_in[2];
    const int*   batch     = (const int*)  d_in[3];
    const float* W_in      = (const float*)d_in[4];
    const float* b_in      = (const float*)d_in[5];
    const float* We        = (const float*)d_in[6];
    const float* be        = (const float*)d_in[7];
    const float* W1        = (const float*)d_in[8];
    const float* b1        = (const float*)d_in[9];
    const float* W2        = (const float*)d_in[10];
    const float* b2        = (const float*)d_in[11];
    const float* W_out     = (const float*)d_in[12];
    const float* b_out     = (const float*)d_in[13];
    float* out = (float*)d_out;

    int N = in_sizes[0] / 32;
    int E = in_sizes[1] / 2;
    int G = out_size;
    const int* src = edge_index;
    const int* dst = edge_index + E;

    float* ph;  cudaGetSymbolAddress((void**)&ph,  g_h);
    float* ph2; cudaGetSymbolAddress((void**)&ph2, g_h2);

    int nb = (N + 255) / 256;

    // g_cnt / g_sums / g_tilectr are zero on entry (zero-init on first call,
    // self-cleaned by fill / final on every call).
    hist_kernel<<<2048, 256>>>(dst, E);
    scan1_kernel<<<nb, 256>>>(N);
    scan2_kernel<<<1, 256>>>(nb, N);
    scan3_kernel<<<nb, 256>>>(N);
    fillproj_kernel<<<FILL_BLKS + PROJ_BLKS, 256>>>(src, dst, edge_attr, E,
                                                    x, W_in, b_in, N);

    int ntiles = (N + TILE_NODES - 1) / TILE_NODES;
    for (int l = 0; l < 5; ++l) {
        const float* hin = (l & 1) ? ph2 : ph;
        float* hout = (l & 1) ? ph : ph2;
        layer_kernel<<<888, 256>>>(hin, hout,
                                   We + l * 4 * 64, be + l * 64,
                                   W1 + l * 64 * 64, b1 + l * 64,
                                   W2 + l * 64 * 64, b2 + l * 64,
                                   batch, (l == 4) ? 1 : 0, N, ntiles, l);
    }

    final_kernel<<<(G * 32 + 255) / 256, 256>>>(out, batch, N, W_out, b_out, G);
}

// round 17
// speedup vs baseline: 1.0611x; 1.0022x over previous
#include <cuda_runtime.h>
#include <cstdint>

#define MAXN 100000
#define MAXE 1600000
#define MAXG 2048
#define H 64
#define NB_MAX ((MAXN + 255) / 256 + 1)

typedef unsigned long long u64;

// f32x2 packed math (Blackwell sm_103a): FFMA2 doubles fp32 FLOPs per instr.
#define FMA2(d, a, b, c) \
    asm("fma.rn.f32x2 %0, %1, %2, %3;" : "=l"(d) : "l"(a), "l"(b), "l"(c))
#define DUP2(d, s) \
    asm("mov.b64 %0, {%1, %1};" : "=l"(d) : "r"(s))
#define UNPK2(lo, hi, s) \
    asm("mov.b64 {%0, %1}, %2;" : "=r"(lo), "=r"(hi) : "l"(s))

// ---------------- scratch (device globals; start zero-initialized) ---------
__device__ float  g_h[MAXN * H];        // node features (ping)
__device__ float  g_h2[MAXN * H];       // node features (pong)
__device__ int    g_cnt[MAXN];          // in-degree histogram (self-cleaned)
__device__ int    g_off[MAXN + 1];      // CSR offsets by dst
__device__ int    g_cur[MAXN];          // running cursors for fill
__device__ int    g_bsum[NB_MAX];       // scan block sums
__device__ int    g_src[MAXE];          // CSR-ordered source node ids
__device__ float4 g_ea[MAXE];           // CSR-ordered edge attributes
__device__ float  g_sums[MAXG * H];     // graph pooling sums (self-cleaned)
__device__ int    g_tilectr[8];         // layer tile-steal counters (self-cleaned)

// ---------------- CSR build -------------------------------------------------
__global__ void hist_kernel(const int* __restrict__ dst, int nedges) {
    for (int i = blockIdx.x * blockDim.x + threadIdx.x; i < nedges; i += gridDim.x * blockDim.x)
        atomicAdd(&g_cnt[dst[i]], 1);
}

// phase 1: block-local exclusive scan of g_cnt chunks; block totals -> g_bsum
__global__ void scan1_kernel(int n) {
    __shared__ int wsum[8];
    int tid = threadIdx.x, lane = tid & 31, w = tid >> 5;
    int i = blockIdx.x * 256 + tid;
    int v = (i < n) ? g_cnt[i] : 0;
    int x = v;
    #pragma unroll
    for (int d = 1; d < 32; d <<= 1) {
        int y = __shfl_up_sync(0xffffffffu, x, d);
        if (lane >= d) x += y;
    }
    if (lane == 31) wsum[w] = x;
    __syncthreads();
    if (w == 0 && lane < 8) {
        int sv = wsum[lane];
        #pragma unroll
        for (int d = 1; d < 8; d <<= 1) {
            int y = __shfl_up_sync(0xffu, sv, d);
            if (lane >= d) sv += y;
        }
        wsum[lane] = sv;
    }
    __syncthreads();
    int pre = (w == 0) ? 0 : wsum[w - 1];
    if (i < n) g_off[i] = pre + x - v;       // local exclusive
    if (tid == 255) g_bsum[blockIdx.x] = wsum[7];
}

// phase 2: single block exclusive-scans the nb block sums in place, total -> g_off[n]
__global__ void scan2_kernel(int nb, int n) {
    __shared__ int wsum[8];
    __shared__ int s_carry;
    int tid = threadIdx.x, lane = tid & 31, w = tid >> 5;
    if (tid == 0) s_carry = 0;
    __syncthreads();
    int nchunk = (nb + 255) >> 8;
    for (int c = 0; c < nchunk; c++) {
        int i = (c << 8) + tid;
        int v = (i < nb) ? g_bsum[i] : 0;
        int x = v;
        #pragma unroll
        for (int d = 1; d < 32; d <<= 1) {
            int y = __shfl_up_sync(0xffffffffu, x, d);
            if (lane >= d) x += y;
        }
        if (lane == 31) wsum[w] = x;
        __syncthreads();
        if (w == 0 && lane < 8) {
            int sv = wsum[lane];
            #pragma unroll
            for (int d = 1; d < 8; d <<= 1) {
                int y = __shfl_up_sync(0xffu, sv, d);
                if (lane >= d) sv += y;
            }
            wsum[lane] = sv;
        }
        __syncthreads();
        int pre = (w == 0) ? 0 : wsum[w - 1];
        int carry = s_carry;
        if (i < nb) g_bsum[i] = carry + pre + x - v;
        __syncthreads();
        if (tid == 0) s_carry = carry + wsum[7];
        __syncthreads();
    }
    if (tid == 0) g_off[n] = s_carry;
}

// phase 3: add block offsets; mirror to g_cur
__global__ void scan3_kernel(int n) {
    int i = blockIdx.x * blockDim.x + threadIdx.x;
    if (i < n) {
        int o = g_off[i] + g_bsum[i >> 8];
        g_off[i] = o;
        g_cur[i] = o;
    }
}

// Merged kernel: blocks [0, FILL_BLKS) fill CSR (and re-zero g_cnt for the
// next call); blocks [FILL_BLKS, FILL_BLKS+PROJ_BLKS) do the input projection.
#define FILL_BLKS 2048
#define PROJ_BLKS 1184
__global__ void fillproj_kernel(const int* __restrict__ src, const int* __restrict__ dst,
                                const float* __restrict__ edge_attr, int nedges,
                                const float* __restrict__ x,
                                const float* __restrict__ W, const float* __restrict__ b,
                                int n) {
    if (blockIdx.x < FILL_BLKS) {
        int i0 = blockIdx.x * blockDim.x + threadIdx.x;
        int stride = FILL_BLKS * blockDim.x;
        for (int i = i0; i < nedges; i += stride) {
            int d = dst[i];
            int p = atomicAdd(&g_cur[d], 1);
            g_src[p] = src[i];
            g_ea[p] = __ldg((const float4*)(edge_attr + (size_t)i * 4));
        }
        for (int i = i0; i < n; i += stride) g_cnt[i] = 0;   // clean for next call
        return;
    }
    // ---- input projection: h = relu(x @ W_in + b_in), x:[n,32] W:[32,64]
    __shared__ float sW[32 * 64];
    __shared__ float sb[64];
    __shared__ float sx[4][32];
    int tid = threadIdx.x;
    for (int i = tid; i < 32 * 64; i += 256) sW[i] = W[i];
    if (tid < 64) sb[tid] = b[tid];
    __syncthreads();
    int s = tid >> 6, j = tid & 63;
    int ntiles = (n + 3) >> 2;
    for (int tile = blockIdx.x - FILL_BLKS; tile < ntiles; tile += PROJ_BLKS) {
        int base = tile * 4;
        if (tid < 128) {
            int node = base + (tid >> 5);
            sx[tid >> 5][tid & 31] = (node < n) ? x[(size_t)node * 32 + (tid & 31)] : 0.f;
        }
        __syncthreads();
        float acc = sb[j];
        #pragma unroll
        for (int k = 0; k < 32; k++) acc = fmaf(sx[s][k], sW[k * 64 + j], acc);
        int node = base + s;
        if (node < n) g_h[(size_t)node * H + j] = fmaxf(acc, 0.f);
        __syncthreads();
    }
}

// ---------------- fused GINE layer: agg (into smem) + MLP + optional pool ---
// Frozen R13 kernel body (125us/layer best known). Grid-size probe only.
#define TILE_NODES 48
__global__ void __launch_bounds__(256) layer_kernel(
        const float* __restrict__ hin, float* __restrict__ hout,
        const float* __restrict__ We, const float* __restrict__ be,
        const float* __restrict__ W1, const float* __restrict__ b1,
        const float* __restrict__ W2, const float* __restrict__ b2,
        const int* __restrict__ batch, int do_pool,
        int n, int ntiles, int slot) {
    __shared__ float sW1[64 * 64];
    __shared__ float sW2[64 * 64];
    __shared__ float sz[TILE_NODES][64];
    __shared__ float sWe[4 * 64];
    __shared__ float sbe[64];
    __shared__ int s_tile;
    int tid = threadIdx.x;
    for (int i = tid; i < 64 * 64; i += 256) { sW1[i] = W1[i]; sW2[i] = W2[i]; }
    if (tid < 256) sWe[tid] = We[tid];
    if (tid < 64) sbe[tid] = be[tid];
    int jgrp = tid & 15;   // MLP output group: j = jgrp*4 (2 f32x2 pairs)
    int i0 = tid >> 4;     // MLP node slot 0..15 (others: i0+16, i0+32)
    int lane = tid & 31;   // agg ids
    int wid = tid >> 5;
    int c0 = lane * 2;
    const u64* b1p = (const u64*)b1;
    const u64* b2p = (const u64*)b2;
    u64 b1lo = __ldg(&b1p[jgrp * 2]), b1hi = __ldg(&b1p[jgrp * 2 + 1]);
    u64 b2lo = __ldg(&b2p[jgrp * 2]), b2hi = __ldg(&b2p[jgrp * 2 + 1]);
    __syncthreads();
    // agg weights into registers (per-lane channel pair)
    float w00 = sWe[0 * 64 + c0], w10 = sWe[1 * 64 + c0], w20 = sWe[2 * 64 + c0], w30 = sWe[3 * 64 + c0];
    float w01 = sWe[0 * 64 + c0 + 1], w11 = sWe[1 * 64 + c0 + 1], w21 = sWe[2 * 64 + c0 + 1], w31 = sWe[3 * 64 + c0 + 1];
    float bb0 = sbe[c0], bb1 = sbe[c0 + 1];
    const ulonglong2* W14 = (const ulonglong2*)sW1;
    const ulonglong2* W24 = (const ulonglong2*)sW2;

    for (;;) {
        if (tid == 0) s_tile = atomicAdd(&g_tilectr[slot], 1);
        __syncthreads();
        int tile = s_tile;
        if (tile >= ntiles) break;
        int base = tile * TILE_NODES;

        // ---- agg phase: warp `wid` aggregates slots [wid*6, wid*6+6)
        #pragma unroll
        for (int q = 0; q < 6; q++) {
            int slotn = wid * 6 + q;
            int node = base + slotn;
            float2 outv = make_float2(0.f, 0.f);
            if (node < n) {
                int s = g_off[node], e = g_off[node + 1];
                float a0 = 0.f, a1 = 0.f, d0 = 0.f, d1 = 0.f;
                float u0 = 0.f, u1 = 0.f, v0 = 0.f, v1 = 0.f;
                int p = s;
                for (; p + 4 <= e; p += 4) {
                    int s0 = __ldg(&g_src[p]);
                    int s1 = __ldg(&g_src[p + 1]);
                    int s2 = __ldg(&g_src[p + 2]);
                    int s3 = __ldg(&g_src[p + 3]);
                    float4 q0 = __ldg(&g_ea[p]);
                    float4 q1 = __ldg(&g_ea[p + 1]);
                    float4 q2 = __ldg(&g_ea[p + 2]);
                    float4 q3 = __ldg(&g_ea[p + 3]);
                    float2 h0 = __ldg((const float2*)(hin + (size_t)s0 * H + c0));
                    float2 h1 = __ldg((const float2*)(hin + (size_t)s1 * H + c0));
                    float2 h2 = __ldg((const float2*)(hin + (size_t)s2 * H + c0));
                    float2 h3 = __ldg((const float2*)(hin + (size_t)s3 * H + c0));
                    float e00 = fmaf(q0.x, w00, fmaf(q0.y, w10, fmaf(q0.z, w20, fmaf(q0.w, w30, bb0))));
                    float e01 = fmaf(q0.x, w01, fmaf(q0.y, w11, fmaf(q0.z, w21, fmaf(q0.w, w31, bb1))));
                    float e10 = fmaf(q1.x, w00, fmaf(q1.y, w10, fmaf(q1.z, w20, fmaf(q1.w, w30, bb0))));
                    float e11 = fmaf(q1.x, w01, fmaf(q1.y, w11, fmaf(q1.z, w21, fmaf(q1.w, w31, bb1))));
                    float e20 = fmaf(q2.x, w00, fmaf(q2.y, w10, fmaf(q2.z, w20, fmaf(q2.w, w30, bb0))));
                    float e21 = fmaf(q2.x, w01, fmaf(q2.y, w11, fmaf(q2.z, w21, fmaf(q2.w, w31, bb1))));
                    float e30 = fmaf(q3.x, w00, fmaf(q3.y, w10, fmaf(q3.z, w20, fmaf(q3.w, w30, bb0))));
                    float e31 = fmaf(q3.x, w01, fmaf(q3.y, w11, fmaf(q3.z, w21, fmaf(q3.w, w31, bb1))));
                    a0 += fmaxf(h0.x + e00, 0.f);  a1 += fmaxf(h0.y + e01, 0.f);
                    u0 += fmaxf(h1.x + e10, 0.f);  u1 += fmaxf(h1.y + e11, 0.f);
                    v0 += fmaxf(h2.x + e20, 0.f);  v1 += fmaxf(h2.y + e21, 0.f);
                    d0 += fmaxf(h3.x + e30, 0.f);  d1 += fmaxf(h3.y + e31, 0.f);
                }
                for (; p < e; ++p) {
                    int s0 = __ldg(&g_src[p]);
                    float4 q0 = __ldg(&g_ea[p]);
                    float2 h0 = __ldg((const float2*)(hin + (size_t)s0 * H + c0));
                    float e00 = fmaf(q0.x, w00, fmaf(q0.y, w10, fmaf(q0.z, w20, fmaf(q0.w, w30, bb0))));
                    float e01 = fmaf(q0.x, w01, fmaf(q0.y, w11, fmaf(q0.z, w21, fmaf(q0.w, w31, bb1))));
                    a0 += fmaxf(h0.x + e00, 0.f);
                    a1 += fmaxf(h0.y + e01, 0.f);
                }
                float2 hd = *(const float2*)(hin + (size_t)node * H + c0);
                outv.x = hd.x + (a0 + u0) + (v0 + d0);
                outv.y = hd.y + (a1 + u1) + (v1 + d1);
            }
            *(float2*)&sz[slotn][c0] = outv;
        }
        __syncthreads();

        // ---- GEMV1: t = relu(z @ W1 + b1)  (packed pairs, 3 nodes/thread)
        u64 A0 = b1lo, A1 = b1hi;
        u64 B0 = b1lo, B1 = b1hi;
        u64 C0 = b1lo, C1 = b1hi;
        #pragma unroll
        for (int k4 = 0; k4 < 16; k4++) {
            float4 z0 = *(const float4*)&sz[i0][k4 * 4];
            float4 z1 = *(const float4*)&sz[i0 + 16][k4 * 4];
            float4 z2 = *(const float4*)&sz[i0 + 32][k4 * 4];
            u64 Z0, Z1, Z2;
            ulonglong2 ww;
            #define STEP1(ZC0, ZC1, ZC2, KK) \
                DUP2(Z0, __float_as_uint(ZC0)); \
                DUP2(Z1, __float_as_uint(ZC1)); \
                DUP2(Z2, __float_as_uint(ZC2)); \
                ww = W14[(k4 * 4 + KK) * 16 + jgrp]; \
                FMA2(A0, Z0, ww.x, A0); FMA2(A1, Z0, ww.y, A1); \
                FMA2(B0, Z1, ww.x, B0); FMA2(B1, Z1, ww.y, B1); \
                FMA2(C0, Z2, ww.x, C0); FMA2(C1, Z2, ww.y, C1);
            STEP1(z0.x, z1.x, z2.x, 0)
            STEP1(z0.y, z1.y, z2.y, 1)
            STEP1(z0.z, z1.z, z2.z, 2)
            STEP1(z0.w, z1.w, z2.w, 3)
            #undef STEP1
        }
        __syncthreads();
        {
            unsigned lo, hi;
            UNPK2(lo, hi, A0);
            *(float2*)&sz[i0][jgrp * 4] =
                make_float2(fmaxf(__uint_as_float(lo), 0.f), fmaxf(__uint_as_float(hi), 0.f));
            UNPK2(lo, hi, A1);
            *(float2*)&sz[i0][jgrp * 4 + 2] =
                make_float2(fmaxf(__uint_as_float(lo), 0.f), fmaxf(__uint_as_float(hi), 0.f));
            UNPK2(lo, hi, B0);
            *(float2*)&sz[i0 + 16][jgrp * 4] =
                make_float2(fmaxf(__uint_as_float(lo), 0.f), fmaxf(__uint_as_float(hi), 0.f));
            UNPK2(lo, hi, B1);
            *(float2*)&sz[i0 + 16][jgrp * 4 + 2] =
                make_float2(fmaxf(__uint_as_float(lo), 0.f), fmaxf(__uint_as_float(hi), 0.f));
            UNPK2(lo, hi, C0);
            *(float2*)&sz[i0 + 32][jgrp * 4] =
                make_float2(fmaxf(__uint_as_float(lo), 0.f), fmaxf(__uint_as_float(hi), 0.f));
            UNPK2(lo, hi, C1);
            *(float2*)&sz[i0 + 32][jgrp * 4 + 2] =
                make_float2(fmaxf(__uint_as_float(lo), 0.f), fmaxf(__uint_as_float(hi), 0.f));
        }
        __syncthreads();
        // ---- GEMV2: h = relu(t @ W2 + b2)
        u64 D0 = b2lo, D1 = b2hi;
        u64 E0 = b2lo, E1 = b2hi;
        u64 F0 = b2lo, F1 = b2hi;
        #pragma unroll
        for (int k4 = 0; k4 < 16; k4++) {
            float4 z0 = *(const float4*)&sz[i0][k4 * 4];
            float4 z1 = *(const float4*)&sz[i0 + 16][k4 * 4];
            float4 z2 = *(const float4*)&sz[i0 + 32][k4 * 4];
            u64 Z0, Z1, Z2;
            ulonglong2 ww;
            #define STEP2(ZC0, ZC1, ZC2, KK) \
                DUP2(Z0, __float_as_uint(ZC0)); \
                DUP2(Z1, __float_as_uint(ZC1)); \
                DUP2(Z2, __float_as_uint(ZC2)); \
                ww = W24[(k4 * 4 + KK) * 16 + jgrp]; \
                FMA2(D0, Z0, ww.x, D0); FMA2(D1, Z0, ww.y, D1); \
                FMA2(E0, Z1, ww.x, E0); FMA2(E1, Z1, ww.y, E1); \
                FMA2(F0, Z2, ww.x, F0); FMA2(F1, Z2, ww.y, F1);
            STEP2(z0.x, z1.x, z2.x, 0)
            STEP2(z0.y, z1.y, z2.y, 1)
            STEP2(z0.z, z1.z, z2.z, 2)
            STEP2(z0.w, z1.w, z2.w, 3)
            #undef STEP2
        }
        float r00, r01, r02, r03, r10, r11, r12, r13, r20, r21, r22, r23;
        {
            unsigned lo, hi;
            UNPK2(lo, hi, D0); r00 = fmaxf(__uint_as_float(lo), 0.f); r01 = fmaxf(__uint_as_float(hi), 0.f);
            UNPK2(lo, hi, D1); r02 = fmaxf(__uint_as_float(lo), 0.f); r03 = fmaxf(__uint_as_float(hi), 0.f);
            UNPK2(lo, hi, E0); r10 = fmaxf(__uint_as_float(lo), 0.f); r11 = fmaxf(__uint_as_float(hi), 0.f);
            UNPK2(lo, hi, E1); r12 = fmaxf(__uint_as_float(lo), 0.f); r13 = fmaxf(__uint_as_float(hi), 0.f);
            UNPK2(lo, hi, F0); r20 = fmaxf(__uint_as_float(lo), 0.f); r21 = fmaxf(__uint_as_float(hi), 0.f);
            UNPK2(lo, hi, F1); r22 = fmaxf(__uint_as_float(lo), 0.f); r23 = fmaxf(__uint_as_float(hi), 0.f);
        }
        int n0 = base + i0, n1 = base + i0 + 16, n2 = base + i0 + 32;
        if (do_pool) {
            if (n0 < n) {
                int g = __ldg(&batch[n0]);
                float* dstp = g_sums + (size_t)g * H + jgrp * 4;
                atomicAdd(dstp + 0, r00); atomicAdd(dstp + 1, r01);
                atomicAdd(dstp + 2, r02); atomicAdd(dstp + 3, r03);
            }
            if (n1 < n) {
                int g = __ldg(&batch[n1]);
                float* dstp = g_sums + (size_t)g * H + jgrp * 4;
                atomicAdd(dstp + 0, r10); atomicAdd(dstp + 1, r11);
                atomicAdd(dstp + 2, r12); atomicAdd(dstp + 3, r13);
            }
            if (n2 < n) {
                int g = __ldg(&batch[n2]);
                float* dstp = g_sums + (size_t)g * H + jgrp * 4;
                atomicAdd(dstp + 0, r20); atomicAdd(dstp + 1, r21);
                atomicAdd(dstp + 2, r22); atomicAdd(dstp + 3, r23);
            }
        } else {
            if (n0 < n) *(float4*)(hout + (size_t)n0 * H + jgrp * 4) = make_float4(r00, r01, r02, r03);
            if (n1 < n) *(float4*)(hout + (size_t)n1 * H + jgrp * 4) = make_float4(r10, r11, r12, r13);
            if (n2 < n) *(float4*)(hout + (size_t)n2 * H + jgrp * 4) = make_float4(r20, r21, r22, r23);
        }
        __syncthreads();
    }
}

// ---------------- final: count (binary search) + mean-pool + LN + linear ----
__global__ void final_kernel(float* __restrict__ out,
                             const int* __restrict__ batch, int n,
                             const float* __restrict__ Wout, const float* __restrict__ bout,
                             int G) {
    int gw = (blockIdx.x * blockDim.x + threadIdx.x) >> 5;
    int lane = threadIdx.x & 31;
    if (gw == 0 && lane < 8) g_tilectr[lane] = 0;   // reset for next call
    if (gw >= G) return;
    int bound = 0;
    if (lane < 2) {
        int key = gw + lane;
        int lo = 0, hi = n;
        while (lo < hi) { int m = (lo + hi) >> 1; if (batch[m] < key) lo = m + 1; else hi = m; }
        bound = lo;
    }
    int start = __shfl_sync(0xffffffffu, bound, 0);
    int end   = __shfl_sync(0xffffffffu, bound, 1);
    float cnt = fmaxf((float)(end - start), 1.f);
    float inv = 1.f / cnt;
    int c0 = 2 * lane;
    float v0 = g_sums[gw * H + c0] * inv;
    float v1 = g_sums[gw * H + c0 + 1] * inv;
    g_sums[gw * H + c0] = 0.f;          // clean for next call
    g_sums[gw * H + c0 + 1] = 0.f;
    float sum = v0 + v1;
    #pragma unroll
    for (int d = 16; d > 0; d >>= 1) sum += __shfl_xor_sync(0xffffffffu, sum, d);
    float mu = sum * (1.f / 64.f);
    float d0 = v0 - mu, d1 = v1 - mu;
    float var = d0 * d0 + d1 * d1;
    #pragma unroll
    for (int d = 16; d > 0; d >>= 1) var += __shfl_xor_sync(0xffffffffu, var, d);
    var *= (1.f / 64.f);
    float rstd = rsqrtf(var + 1e-5f);
    float y = d0 * rstd * Wout[c0] + d1 * rstd * Wout[c0 + 1];
    #pragma unroll
    for (int d = 16; d > 0; d >>= 1) y += __shfl_xor_sync(0xffffffffu, y, d);
    if (lane == 0) out[gw] = y + bout[0];
}

// ---------------- driver -----------------------------------------------------
extern "C" void kernel_launch(void* const* d_in, const int* in_sizes, int n_in,
                              void* d_out, int out_size) {
    const float* x         = (const float*)d_in[0];
    const int*   edge_index= (const int*)  d_in[1];
    const float* edge_attr = (const float*)d_in[2];
    const int*   batch     = (const int*)  d_in[3];
    const float* W_in      = (const float*)d_in[4];
    const float* b_in      = (const float*)d_in[5];
    const float* We        = (const float*)d_in[6];
    const float* be        = (const float*)d_in[7];
    const float* W1        = (const float*)d_in[8];
    const float* b1        = (const float*)d_in[9];
    const float* W2        = (const float*)d_in[10];
    const float* b2        = (const float*)d_in[11];
    const float* W_out     = (const float*)d_in[12];
    const float* b_out     = (const float*)d_in[13];
    float* out = (float*)d_out;

    int N = in_sizes[0] / 32;
    int E = in_sizes[1] / 2;
    int G = out_size;
    const int* src = edge_index;
    const int* dst = edge_index + E;

    float* ph;  cudaGetSymbolAddress((void**)&ph,  g_h);
    float* ph2; cudaGetSymbolAddress((void**)&ph2, g_h2);

    int nb = (N + 255) / 256;

    // g_cnt / g_sums / g_tilectr are zero on entry (zero-init on first call,
    // self-cleaned by fill / final on every call).
    hist_kernel<<<4096, 256>>>(dst, E);
    scan1_kernel<<<nb, 256>>>(N);
    scan2_kernel<<<1, 256>>>(nb, N);
    scan3_kernel<<<nb, 256>>>(N);
    fillproj_kernel<<<FILL_BLKS + PROJ_BLKS, 256>>>(src, dst, edge_attr, E,
                                                    x, W_in, b_in, N);

    int ntiles = (N + TILE_NODES - 1) / TILE_NODES;
    for (int l = 0; l < 5; ++l) {
        const float* hin = (l & 1) ? ph2 : ph;
        float* hout = (l & 1) ? ph : ph2;
        layer_kernel<<<1184, 256>>>(hin, hout,
                                    We + l * 4 * 64, be + l * 64,
                                    W1 + l * 64 * 64, b1 + l * 64,
                                    W2 + l * 64 * 64, b2 + l * 64,
                                    batch, (l == 4) ? 1 : 0, N, ntiles, l);
    }

    final_kernel<<<(G * 32 + 255) / 256, 256>>>(out, batch, N, W_out, b_out, G);
}